// round 1
// baseline (speedup 1.0000x reference)
#include <cuda_runtime.h>
#include <cstdint>

#define BB 2
#define NN 2048
#define DD 512
#define HH 8
#define HD 64
#define ROWS (BB*NN)

// Scratch (no allocations allowed): Q, K, V projections + gate vector c
__device__ float g_QKV[3][(size_t)ROWS * DD];
__device__ float g_c[ROWS];

// ---------------------------------------------------------------------------
// Fast exp on the FMA pipe (no MUFU). Valid for x <= 0 (clamped at -80).
// exp(x) = 2^(x*log2e); split integer/frac via round-to-int trick, degree-5
// Taylor for 2^f on [-0.5, 0.5] (rel err ~2e-6).
// ---------------------------------------------------------------------------
__device__ __forceinline__ float fexp(float x) {
    x = fmaxf(x, -80.0f);
    float y = x * 1.4426950408889634f;
    float r = __fadd_rn(y, 12582912.0f);        // 1.5*2^23: rounds y to int
    float n = __fadd_rn(r, -12582912.0f);
    float f = y - n;                             // in [-0.5, 0.5]
    float p = 1.3333558e-3f;
    p = fmaf(p, f, 9.6181291e-3f);
    p = fmaf(p, f, 5.5504109e-2f);
    p = fmaf(p, f, 2.4022651e-1f);
    p = fmaf(p, f, 6.9314718e-1f);
    p = fmaf(p, f, 1.0f);
    int ei = __float_as_int(r) - 0x4B400000;     // integer part (<= 0 here)
    float sc = __int_as_float((127 + ei) << 23); // 2^ei
    return p * sc;
}

// ---------------------------------------------------------------------------
// Kernel 1: fused QKV projection. C = X @ W + b, W selected by blockIdx.z.
// 64x64 output tile, BK=16, 256 threads, 4x4 register tile per thread.
// ---------------------------------------------------------------------------
__global__ __launch_bounds__(256)
void qkv_gemm(const float* __restrict__ X,
              const float* __restrict__ Wq, const float* __restrict__ bq,
              const float* __restrict__ Wk, const float* __restrict__ bk,
              const float* __restrict__ Wv, const float* __restrict__ bv)
{
    __shared__ float As[16][68];   // As[k][m] (A transposed)
    __shared__ float Bs[16][68];   // Bs[k][n]

    int z = blockIdx.z;
    const float* W    = (z == 0) ? Wq : (z == 1) ? Wk : Wv;
    const float* bias = (z == 0) ? bq : (z == 1) ? bk : bv;
    float* C = g_QKV[z];

    int row0 = blockIdx.y * 64;
    int col0 = blockIdx.x * 64;
    int t  = threadIdx.x;
    int tx = t & 15, ty = t >> 4;
    int am = t >> 2, ak = (t & 3) * 4;

    float acc[4][4] = {};

    for (int k0 = 0; k0 < DD; k0 += 16) {
        float4 a = *(const float4*)(X + (size_t)(row0 + am) * DD + k0 + ak);
        As[ak + 0][am] = a.x;
        As[ak + 1][am] = a.y;
        As[ak + 2][am] = a.z;
        As[ak + 3][am] = a.w;
        float4 b4 = *(const float4*)(W + (size_t)(k0 + ty) * DD + col0 + tx * 4);
        *(float4*)&Bs[ty][tx * 4] = b4;
        __syncthreads();

        #pragma unroll
        for (int k = 0; k < 16; ++k) {
            float4 av = *(float4*)&As[k][ty * 4];
            float4 bw = *(float4*)&Bs[k][tx * 4];
            float qa[4] = {av.x, av.y, av.z, av.w};
            float ba[4] = {bw.x, bw.y, bw.z, bw.w};
            #pragma unroll
            for (int ii = 0; ii < 4; ++ii)
                #pragma unroll
                for (int jj = 0; jj < 4; ++jj)
                    acc[ii][jj] = fmaf(qa[ii], ba[jj], acc[ii][jj]);
        }
        __syncthreads();
    }

    float4 bb = *(const float4*)(bias + col0 + tx * 4);
    #pragma unroll
    for (int ii = 0; ii < 4; ++ii) {
        float4 o;
        o.x = acc[ii][0] + bb.x;
        o.y = acc[ii][1] + bb.y;
        o.z = acc[ii][2] + bb.z;
        o.w = acc[ii][3] + bb.w;
        *(float4*)(C + (size_t)(row0 + ty * 4 + ii) * DD + col0 + tx * 4) = o;
    }
}

// ---------------------------------------------------------------------------
// Kernel 2: c[row] = x[row] . w_g[D:2D]   (the x_i/a_i part cancels in softmax)
// ---------------------------------------------------------------------------
__global__ __launch_bounds__(256)
void gate_kernel(const float* __restrict__ x, const float* __restrict__ wg)
{
    int row  = blockIdx.x * 8 + (threadIdx.x >> 5);
    int lane = threadIdx.x & 31;
    const float* xr = x + (size_t)row * DD;
    const float* w2 = wg + DD;
    float s = 0.f;
    #pragma unroll 4
    for (int d = lane; d < DD; d += 32) s = fmaf(xr[d], w2[d], s);
    #pragma unroll
    for (int off = 16; off > 0; off >>= 1)
        s += __shfl_xor_sync(0xffffffffu, s, off);
    if (lane == 0) g_c[row] = s;
}

// ---------------------------------------------------------------------------
// Kernel 3: fused flash-style attention + gate-bias + adjacency + residual.
// Block = (b, h, 64-query tile), 256 threads (16x16), 4x4 micro-tiles.
// exp(t + log(adj+eps) - m) == (adj+eps) * exp(t - m): no logs anywhere.
// ---------------------------------------------------------------------------
__global__ __launch_bounds__(256)
void attn_kernel(const float* __restrict__ x, const float* __restrict__ adj,
                 float* __restrict__ out)
{
    extern __shared__ float sm[];
    float* Qs = sm;              // [64][68]  Qs[d*68 + i]  (transposed)
    float* KP = sm + 64 * 68;    // Ks[d*68 + j] during S; Ps[i*68 + j] during PV
    float* Vs = sm + 2 * 64 * 68;// [64][68]  Vs[j*68 + d]

    int t  = threadIdx.x;
    int tx = t & 15, ty = t >> 4;
    int i0 = blockIdx.x * 64;
    int h  = blockIdx.y;
    int b  = blockIdx.z;

    const float* Qg = g_QKV[0] + (size_t)b * NN * DD + h * HD;
    const float* Kg = g_QKV[1] + (size_t)b * NN * DD + h * HD;
    const float* Vg = g_QKV[2] + (size_t)b * NN * DD + h * HD;
    const float* cv   = g_c + b * NN;
    const float* adjb = adj + (size_t)b * NN * NN;

    // Load Q tile transposed: Qs[d][i]
    #pragma unroll
    for (int r = 0; r < 4; ++r) {
        int i  = (t >> 4) + r * 16;
        int dq = (t & 15) * 4;
        float4 q = *(const float4*)(Qg + (size_t)(i0 + i) * DD + dq);
        Qs[(dq + 0) * 68 + i] = q.x;
        Qs[(dq + 1) * 68 + i] = q.y;
        Qs[(dq + 2) * 68 + i] = q.z;
        Qs[(dq + 3) * 68 + i] = q.w;
    }

    float m_run[4], l_run[4], o[4][4];
    #pragma unroll
    for (int ii = 0; ii < 4; ++ii) {
        m_run[ii] = -1e30f; l_run[ii] = 0.f;
        #pragma unroll
        for (int jj = 0; jj < 4; ++jj) o[ii][jj] = 0.f;
    }

    for (int jt = 0; jt < NN / 64; ++jt) {
        int j0 = jt * 64;
        __syncthreads();   // previous PV (and Q store) complete before overwrite

        // Load K transposed (Ks[d][j]) and V natural (Vs[j][d])
        #pragma unroll
        for (int r = 0; r < 4; ++r) {
            int j  = (t >> 4) + r * 16;
            int dq = (t & 15) * 4;
            float4 k4 = *(const float4*)(Kg + (size_t)(j0 + j) * DD + dq);
            KP[(dq + 0) * 68 + j] = k4.x;
            KP[(dq + 1) * 68 + j] = k4.y;
            KP[(dq + 2) * 68 + j] = k4.z;
            KP[(dq + 3) * 68 + j] = k4.w;
            float4 v4 = *(const float4*)(Vg + (size_t)(j0 + j) * DD + dq);
            *(float4*)&Vs[j * 68 + dq] = v4;
        }
        __syncthreads();

        // S = Q K^T  (4x4 per thread)
        float s[4][4] = {};
        #pragma unroll 8
        for (int k = 0; k < 64; ++k) {
            float4 q  = *(float4*)&Qs[k * 68 + ty * 4];
            float4 kk = *(float4*)&KP[k * 68 + tx * 4];
            float qa[4] = {q.x, q.y, q.z, q.w};
            float ka[4] = {kk.x, kk.y, kk.z, kk.w};
            #pragma unroll
            for (int ii = 0; ii < 4; ++ii)
                #pragma unroll
                for (int jj = 0; jj < 4; ++jj)
                    s[ii][jj] = fmaf(qa[ii], ka[jj], s[ii][jj]);
        }

        // t = s/sqrt(hd) + c_j  (a_i + b_g cancel in softmax); tile row max
        float4 cj4 = *(const float4*)(cv + j0 + tx * 4);
        float cj[4] = {cj4.x, cj4.y, cj4.z, cj4.w};
        float tt[4][4], mt[4];
        #pragma unroll
        for (int ii = 0; ii < 4; ++ii) {
            mt[ii] = -1e30f;
            #pragma unroll
            for (int jj = 0; jj < 4; ++jj) {
                tt[ii][jj] = fmaf(s[ii][jj], 0.125f, cj[jj]);
                mt[ii] = fmaxf(mt[ii], tt[ii][jj]);
            }
        }
        #pragma unroll
        for (int off = 8; off > 0; off >>= 1)
            #pragma unroll
            for (int ii = 0; ii < 4; ++ii)
                mt[ii] = fmaxf(mt[ii], __shfl_xor_sync(0xffffffffu, mt[ii], off));

        float p[4][4], rs[4], al[4];
        #pragma unroll
        for (int ii = 0; ii < 4; ++ii) {
            float mnew = fmaxf(m_run[ii], mt[ii]);
            al[ii] = fexp(m_run[ii] - mnew);
            m_run[ii] = mnew;
            rs[ii] = 0.f;
        }

        // p = (adj + eps) * exp(t - m); adjacency straight from gmem
        #pragma unroll
        for (int ii = 0; ii < 4; ++ii) {
            float4 a4 = *(const float4*)(adjb +
                (size_t)(i0 + ty * 4 + ii) * NN + j0 + tx * 4);
            float aa[4] = {a4.x, a4.y, a4.z, a4.w};
            #pragma unroll
            for (int jj = 0; jj < 4; ++jj) {
                float pv = fexp(tt[ii][jj] - m_run[ii]) * (aa[jj] + 1e-9f);
                p[ii][jj] = pv;
                rs[ii] += pv;
            }
        }
        #pragma unroll
        for (int off = 8; off > 0; off >>= 1)
            #pragma unroll
            for (int ii = 0; ii < 4; ++ii)
                rs[ii] += __shfl_xor_sync(0xffffffffu, rs[ii], off);

        #pragma unroll
        for (int ii = 0; ii < 4; ++ii) {
            l_run[ii] = l_run[ii] * al[ii] + rs[ii];
            #pragma unroll
            for (int jj = 0; jj < 4; ++jj) o[ii][jj] *= al[ii];
        }

        __syncthreads();   // everyone finished reading KP as K
        // Write P (reusing K's buffer): Ps[i][j]
        #pragma unroll
        for (int ii = 0; ii < 4; ++ii)
            #pragma unroll
            for (int jj = 0; jj < 4; ++jj)
                KP[(ty * 4 + ii) * 68 + tx * 4 + jj] = p[ii][jj];
        __syncthreads();

        // O += P @ V
        #pragma unroll 8
        for (int j = 0; j < 64; ++j) {
            float4 v = *(float4*)&Vs[j * 68 + tx * 4];
            float va[4] = {v.x, v.y, v.z, v.w};
            #pragma unroll
            for (int ii = 0; ii < 4; ++ii) {
                float pij = KP[(ty * 4 + ii) * 68 + j];
                #pragma unroll
                for (int dd = 0; dd < 4; ++dd)
                    o[ii][dd] = fmaf(pij, va[dd], o[ii][dd]);
            }
        }
    }

    // Epilogue: normalize + residual
    #pragma unroll
    for (int ii = 0; ii < 4; ++ii) {
        int i = i0 + ty * 4 + ii;
        float inv = __fdividef(1.0f, l_run[ii]);
        float4 xr = *(const float4*)(x + ((size_t)b * NN + i) * DD + h * HD + tx * 4);
        float4 ov;
        ov.x = fmaf(o[ii][0], inv, xr.x);
        ov.y = fmaf(o[ii][1], inv, xr.y);
        ov.z = fmaf(o[ii][2], inv, xr.z);
        ov.w = fmaf(o[ii][3], inv, xr.w);
        *(float4*)(out + ((size_t)b * NN + i) * DD + h * HD + tx * 4) = ov;
    }
}

// ---------------------------------------------------------------------------
extern "C" void kernel_launch(void* const* d_in, const int* in_sizes, int n_in,
                              void* d_out, int out_size)
{
    const float* x   = (const float*)d_in[0];
    const float* adj = (const float*)d_in[1];
    const float* Wq  = (const float*)d_in[2];
    const float* bq  = (const float*)d_in[3];
    const float* Wk  = (const float*)d_in[4];
    const float* bk  = (const float*)d_in[5];
    const float* Wv  = (const float*)d_in[6];
    const float* bv  = (const float*)d_in[7];
    const float* wg  = (const float*)d_in[8];
    // d_in[9] (b_g) cancels inside the softmax; unused.
    float* out = (float*)d_out;

    const int attn_smem = 3 * 64 * 68 * (int)sizeof(float);  // 52224 B
    cudaFuncSetAttribute((const void*)attn_kernel,
                         cudaFuncAttributeMaxDynamicSharedMemorySize, attn_smem);

    qkv_gemm<<<dim3(DD / 64, ROWS / 64, 3), 256>>>(x, Wq, bq, Wk, bk, Wv, bv);
    gate_kernel<<<ROWS / 8, 256>>>(x, wg);
    attn_kernel<<<dim3(NN / 64, HH, BB), 256, attn_smem>>>(x, adj, out);
}

// round 2
// speedup vs baseline: 1.8572x; 1.8572x over previous
#include <cuda_runtime.h>
#include <cstdint>

#define BB 2
#define NN 2048
#define DD 512
#define HH 8
#define HD 64
#define ROWS (BB*NN)

// Scratch (no allocations allowed): Q, K, V projections + gate vector c
__device__ float g_QKV[3][(size_t)ROWS * DD];
__device__ float g_c[ROWS];

// ---------------------------------------------------------------------------
// Fast exp on the FMA pipe (no MUFU). Valid for x <= 0 (clamped at -80).
// ---------------------------------------------------------------------------
__device__ __forceinline__ float fexp(float x) {
    x = fmaxf(x, -80.0f);
    float y = x * 1.4426950408889634f;
    float r = __fadd_rn(y, 12582912.0f);
    float n = __fadd_rn(r, -12582912.0f);
    float f = y - n;
    float p = 1.3333558e-3f;
    p = fmaf(p, f, 9.6181291e-3f);
    p = fmaf(p, f, 5.5504109e-2f);
    p = fmaf(p, f, 2.4022651e-1f);
    p = fmaf(p, f, 6.9314718e-1f);
    p = fmaf(p, f, 1.0f);
    int ei = __float_as_int(r) - 0x4B400000;
    float sc = __int_as_float((127 + ei) << 23);
    return p * sc;
}

// ---------------------------------------------------------------------------
// tf32 helpers (m16n8k8 mma.sync, fp32 accumulate)
// ---------------------------------------------------------------------------
__device__ __forceinline__ uint32_t to_tf32(float f) {
    uint32_t r;
    asm("cvt.rna.tf32.f32 %0, %1;" : "=r"(r) : "f"(f));
    return r;
}

__device__ __forceinline__ void mma8(float* d, const uint32_t* a,
                                     const uint32_t* b, const float* c) {
    asm("mma.sync.aligned.m16n8k8.row.col.f32.tf32.tf32.f32 "
        "{%0,%1,%2,%3}, {%4,%5,%6,%7}, {%8,%9}, {%10,%11,%12,%13};"
        : "=f"(d[0]), "=f"(d[1]), "=f"(d[2]), "=f"(d[3])
        : "r"(a[0]), "r"(a[1]), "r"(a[2]), "r"(a[3]),
          "r"(b[0]), "r"(b[1]),
          "f"(c[0]), "f"(c[1]), "f"(c[2]), "f"(c[3]));
}

// ---------------------------------------------------------------------------
// Kernel 1: fused QKV projection via tf32 tensor cores.
// C = X @ W + b, W selected by blockIdx.z. 128x64 tile, BK=32, 256 threads.
// Warp grid 4x2; each warp computes 32x32 (2 m-tiles x 4 n-tiles of m16n8k8).
// ---------------------------------------------------------------------------
__global__ __launch_bounds__(256)
void qkv_gemm(const float* __restrict__ X,
              const float* __restrict__ Wq, const float* __restrict__ bq,
              const float* __restrict__ Wk, const float* __restrict__ bk,
              const float* __restrict__ Wv, const float* __restrict__ bv)
{
    __shared__ float Xs[128 * 36];   // [row][k], stride 36
    __shared__ float Ws[32 * 72];    // [k][n],  stride 72 (conflict-free B frags)

    int z = blockIdx.z;
    const float* W    = (z == 0) ? Wq : (z == 1) ? Wk : Wv;
    const float* bias = (z == 0) ? bq : (z == 1) ? bk : bv;
    float* C = g_QKV[z];

    int row0 = blockIdx.y * 128;
    int col0 = blockIdx.x * 64;
    int tid  = threadIdx.x;
    int warp = tid >> 5, lane = tid & 31;
    int g = lane >> 2, t4 = lane & 3;
    int wm = (warp & 3) * 32;       // warp row offset in tile
    int wn = (warp >> 2) * 32;      // warp col offset in tile

    float acc[2][4][4] = {};

    for (int k0 = 0; k0 < DD; k0 += 32) {
        // stage X tile 128x32 (1024 float4, 4 per thread)
        #pragma unroll
        for (int it = 0; it < 4; ++it) {
            int fi = tid + it * 256;
            int r = fi >> 3, c4 = (fi & 7) * 4;
            float4 v = *(const float4*)(X + (size_t)(row0 + r) * DD + k0 + c4);
            *(float4*)&Xs[r * 36 + c4] = v;
        }
        // stage W tile 32x64 (512 float4, 2 per thread)
        #pragma unroll
        for (int it = 0; it < 2; ++it) {
            int fi = tid + it * 256;
            int r = fi >> 4, c4 = (fi & 15) * 4;
            float4 v = *(const float4*)(W + (size_t)(k0 + r) * DD + col0 + c4);
            *(float4*)&Ws[r * 72 + c4] = v;
        }
        __syncthreads();

        #pragma unroll
        for (int ch = 0; ch < 4; ++ch) {
            int kk = ch * 8;
            uint32_t a[2][4];
            #pragma unroll
            for (int m = 0; m < 2; ++m) {
                int rb = wm + m * 16;
                a[m][0] = to_tf32(Xs[(rb + g) * 36 + kk + t4]);
                a[m][1] = to_tf32(Xs[(rb + g + 8) * 36 + kk + t4]);
                a[m][2] = to_tf32(Xs[(rb + g) * 36 + kk + t4 + 4]);
                a[m][3] = to_tf32(Xs[(rb + g + 8) * 36 + kk + t4 + 4]);
            }
            uint32_t bf[4][2];
            #pragma unroll
            for (int n = 0; n < 4; ++n) {
                int cb = wn + n * 8 + g;
                bf[n][0] = to_tf32(Ws[(kk + t4) * 72 + cb]);
                bf[n][1] = to_tf32(Ws[(kk + t4 + 4) * 72 + cb]);
            }
            #pragma unroll
            for (int m = 0; m < 2; ++m)
                #pragma unroll
                for (int n = 0; n < 4; ++n)
                    mma8(acc[m][n], a[m], bf[n], acc[m][n]);
        }
        __syncthreads();
    }

    // epilogue: + bias, write fp32
    #pragma unroll
    for (int n = 0; n < 4; ++n) {
        int col = col0 + wn + n * 8 + 2 * t4;
        float2 bb = *(const float2*)(bias + col);
        #pragma unroll
        for (int m = 0; m < 2; ++m) {
            int r0 = row0 + wm + m * 16 + g;
            float2 o0 = {acc[m][n][0] + bb.x, acc[m][n][1] + bb.y};
            float2 o1 = {acc[m][n][2] + bb.x, acc[m][n][3] + bb.y};
            *(float2*)(C + (size_t)r0 * DD + col) = o0;
            *(float2*)(C + (size_t)(r0 + 8) * DD + col) = o1;
        }
    }
}

// ---------------------------------------------------------------------------
// Kernel 2: c[row] = x[row] . w_g[D:2D]   (a_i + b_g cancel in softmax)
// ---------------------------------------------------------------------------
__global__ __launch_bounds__(256)
void gate_kernel(const float* __restrict__ x, const float* __restrict__ wg)
{
    int row  = blockIdx.x * 8 + (threadIdx.x >> 5);
    int lane = threadIdx.x & 31;
    const float* xr = x + (size_t)row * DD;
    const float* w2 = wg + DD;
    float s = 0.f;
    #pragma unroll 4
    for (int d = lane; d < DD; d += 32) s = fmaf(xr[d], w2[d], s);
    #pragma unroll
    for (int off = 16; off > 0; off >>= 1)
        s += __shfl_xor_sync(0xffffffffu, s, off);
    if (lane == 0) g_c[row] = s;
}

// ---------------------------------------------------------------------------
// Kernel 3: flash attention on tf32 tensor cores.
// CTA = (64-query tile, h, b), 128 threads = 4 warps x 16 query rows.
// exp(t + log(adj+eps) - m) == (adj+eps)*exp(t - m): no logs anywhere.
// Q fragments live in registers for the whole kernel.
// ---------------------------------------------------------------------------
__global__ __launch_bounds__(128)
void attn_kernel(const float* __restrict__ x, const float* __restrict__ adj,
                 float* __restrict__ out)
{
    extern __shared__ float sm[];
    float* Ks = sm;                     // [64][68]
    float* Vs = sm + 64 * 68;           // [64][72]
    float* Ps = sm + 64 * 68 + 64 * 72; // [64][68]  (Q staging, then P)

    int tid  = threadIdx.x;
    int warp = tid >> 5, lane = tid & 31;
    int g = lane >> 2, t4 = lane & 3;
    int qr = warp * 16;                 // warp's query-row base in tile
    int i0 = blockIdx.x * 64;
    int h  = blockIdx.y;
    int b  = blockIdx.z;

    const float* Qg = g_QKV[0] + (size_t)b * NN * DD + h * HD;
    const float* Kg = g_QKV[1] + (size_t)b * NN * DD + h * HD;
    const float* Vg = g_QKV[2] + (size_t)b * NN * DD + h * HD;
    const float* cv   = g_c + b * NN;
    const float* adjb = adj + (size_t)b * NN * NN;

    // ---- Stage Q tile (64x64) into Ps, convert to A fragments in regs ----
    #pragma unroll
    for (int it = 0; it < 8; ++it) {
        int fi = tid + it * 128;
        int r = fi >> 4, c4 = (fi & 15) * 4;
        float4 v = *(const float4*)(Qg + (size_t)(i0 + r) * DD + c4);
        *(float4*)&Ps[r * 68 + c4] = v;
    }
    __syncthreads();

    uint32_t qa[8][4];
    #pragma unroll
    for (int ch = 0; ch < 8; ++ch) {
        int kk = ch * 8;
        qa[ch][0] = to_tf32(Ps[(qr + g) * 68 + kk + t4]);
        qa[ch][1] = to_tf32(Ps[(qr + g + 8) * 68 + kk + t4]);
        qa[ch][2] = to_tf32(Ps[(qr + g) * 68 + kk + t4 + 4]);
        qa[ch][3] = to_tf32(Ps[(qr + g + 8) * 68 + kk + t4 + 4]);
    }

    float m0 = -1e30f, m1 = -1e30f, l0 = 0.f, l1 = 0.f;
    float o[8][4] = {};

    for (int jt = 0; jt < NN / 64; ++jt) {
        int j0 = jt * 64;
        __syncthreads();   // previous iter's K/V reads complete

        // load K (stride 68) and V (stride 72), 8 float4 each per thread
        #pragma unroll
        for (int it = 0; it < 8; ++it) {
            int fi = tid + it * 128;
            int r = fi >> 4, c4 = (fi & 15) * 4;
            float4 k4 = *(const float4*)(Kg + (size_t)(j0 + r) * DD + c4);
            *(float4*)&Ks[r * 68 + c4] = k4;
            float4 v4 = *(const float4*)(Vg + (size_t)(j0 + r) * DD + c4);
            *(float4*)&Vs[r * 72 + c4] = v4;
        }
        __syncthreads();

        // ---- S = Q K^T : warp computes 16x64 (8 n-tiles) ----
        float s[8][4] = {};
        #pragma unroll
        for (int ch = 0; ch < 8; ++ch) {
            int kk = ch * 8;
            #pragma unroll
            for (int n = 0; n < 8; ++n) {
                uint32_t bf[2];
                bf[0] = to_tf32(Ks[(n * 8 + g) * 68 + kk + t4]);
                bf[1] = to_tf32(Ks[(n * 8 + g) * 68 + kk + t4 + 4]);
                mma8(s[n], qa[ch], bf, s[n]);
            }
        }

        // ---- t = s/8 + c_j ; row max in fragment layout ----
        float mt0 = -1e30f, mt1 = -1e30f;
        #pragma unroll
        for (int n = 0; n < 8; ++n) {
            float2 cc = *(const float2*)(cv + j0 + n * 8 + 2 * t4);
            s[n][0] = fmaf(s[n][0], 0.125f, cc.x);
            s[n][1] = fmaf(s[n][1], 0.125f, cc.y);
            s[n][2] = fmaf(s[n][2], 0.125f, cc.x);
            s[n][3] = fmaf(s[n][3], 0.125f, cc.y);
            mt0 = fmaxf(mt0, fmaxf(s[n][0], s[n][1]));
            mt1 = fmaxf(mt1, fmaxf(s[n][2], s[n][3]));
        }
        mt0 = fmaxf(mt0, __shfl_xor_sync(0xffffffffu, mt0, 1));
        mt0 = fmaxf(mt0, __shfl_xor_sync(0xffffffffu, mt0, 2));
        mt1 = fmaxf(mt1, __shfl_xor_sync(0xffffffffu, mt1, 1));
        mt1 = fmaxf(mt1, __shfl_xor_sync(0xffffffffu, mt1, 2));

        float m0n = fmaxf(m0, mt0), m1n = fmaxf(m1, mt1);
        float a0 = fexp(m0 - m0n), a1 = fexp(m1 - m1n);
        m0 = m0n; m1 = m1n;

        // ---- p = (adj+eps)*exp(t-m); store P to smem; row sums ----
        float rs0 = 0.f, rs1 = 0.f;
        int r0 = i0 + qr + g, r1 = r0 + 8;
        #pragma unroll
        for (int n = 0; n < 8; ++n) {
            int jc = j0 + n * 8 + 2 * t4;
            float2 ad0 = *(const float2*)(adjb + (size_t)r0 * NN + jc);
            float2 ad1 = *(const float2*)(adjb + (size_t)r1 * NN + jc);
            float p00 = fexp(s[n][0] - m0) * (ad0.x + 1e-9f);
            float p01 = fexp(s[n][1] - m0) * (ad0.y + 1e-9f);
            float p10 = fexp(s[n][2] - m1) * (ad1.x + 1e-9f);
            float p11 = fexp(s[n][3] - m1) * (ad1.y + 1e-9f);
            rs0 += p00 + p01; rs1 += p10 + p11;
            float2 w0 = {p00, p01}, w1 = {p10, p11};
            *(float2*)&Ps[(qr + g) * 68 + n * 8 + 2 * t4] = w0;
            *(float2*)&Ps[(qr + g + 8) * 68 + n * 8 + 2 * t4] = w1;
        }
        rs0 += __shfl_xor_sync(0xffffffffu, rs0, 1);
        rs0 += __shfl_xor_sync(0xffffffffu, rs0, 2);
        rs1 += __shfl_xor_sync(0xffffffffu, rs1, 1);
        rs1 += __shfl_xor_sync(0xffffffffu, rs1, 2);
        l0 = l0 * a0 + rs0;
        l1 = l1 * a1 + rs1;

        // rescale O
        #pragma unroll
        for (int n = 0; n < 8; ++n) {
            o[n][0] *= a0; o[n][1] *= a0; o[n][2] *= a1; o[n][3] *= a1;
        }
        __syncwarp();   // P rows are warp-private; warp-level visibility only

        // ---- O += P @ V ----
        #pragma unroll
        for (int ch = 0; ch < 8; ++ch) {
            int kk = ch * 8;
            uint32_t pa[4];
            pa[0] = to_tf32(Ps[(qr + g) * 68 + kk + t4]);
            pa[1] = to_tf32(Ps[(qr + g + 8) * 68 + kk + t4]);
            pa[2] = to_tf32(Ps[(qr + g) * 68 + kk + t4 + 4]);
            pa[3] = to_tf32(Ps[(qr + g + 8) * 68 + kk + t4 + 4]);
            #pragma unroll
            for (int n = 0; n < 8; ++n) {
                uint32_t bf[2];
                bf[0] = to_tf32(Vs[(kk + t4) * 72 + n * 8 + g]);
                bf[1] = to_tf32(Vs[(kk + t4 + 4) * 72 + n * 8 + g]);
                mma8(o[n], pa, bf, o[n]);
            }
        }
    }

    // ---- epilogue: normalize + residual ----
    float inv0 = __fdividef(1.0f, l0);
    float inv1 = __fdividef(1.0f, l1);
    int r0 = i0 + qr + g, r1 = r0 + 8;
    #pragma unroll
    for (int n = 0; n < 8; ++n) {
        int col = h * HD + n * 8 + 2 * t4;
        float2 x0 = *(const float2*)(x + ((size_t)b * NN + r0) * DD + col);
        float2 x1 = *(const float2*)(x + ((size_t)b * NN + r1) * DD + col);
        float2 o0 = {fmaf(o[n][0], inv0, x0.x), fmaf(o[n][1], inv0, x0.y)};
        float2 o1 = {fmaf(o[n][2], inv1, x1.x), fmaf(o[n][3], inv1, x1.y)};
        *(float2*)(out + ((size_t)b * NN + r0) * DD + col) = o0;
        *(float2*)(out + ((size_t)b * NN + r1) * DD + col) = o1;
    }
}

// ---------------------------------------------------------------------------
extern "C" void kernel_launch(void* const* d_in, const int* in_sizes, int n_in,
                              void* d_out, int out_size)
{
    const float* x   = (const float*)d_in[0];
    const float* adj = (const float*)d_in[1];
    const float* Wq  = (const float*)d_in[2];
    const float* bq  = (const float*)d_in[3];
    const float* Wk  = (const float*)d_in[4];
    const float* bk  = (const float*)d_in[5];
    const float* Wv  = (const float*)d_in[6];
    const float* bv  = (const float*)d_in[7];
    const float* wg  = (const float*)d_in[8];
    // d_in[9] (b_g) cancels inside the softmax; unused.
    float* out = (float*)d_out;

    const int attn_smem = (64 * 68 + 64 * 72 + 64 * 68) * (int)sizeof(float); // 53248
    cudaFuncSetAttribute((const void*)attn_kernel,
                         cudaFuncAttributeMaxDynamicSharedMemorySize, attn_smem);

    qkv_gemm<<<dim3(DD / 64, ROWS / 128, 3), 256>>>(x, Wq, bq, Wk, bk, Wv, bv);
    gate_kernel<<<ROWS / 8, 256>>>(x, wg);
    attn_kernel<<<dim3(NN / 64, HH, BB), 128, attn_smem>>>(x, adj, out);
}

// round 3
// speedup vs baseline: 2.9091x; 1.5664x over previous
#include <cuda_runtime.h>
#include <cstdint>

#define BB 2
#define NN 2048
#define DD 512
#define HH 8
#define HD 64
#define ROWS (BB*NN)

// Scratch (no allocations allowed): Q, K, V projections + gate vector c
__device__ float g_QKV[3][(size_t)ROWS * DD];
__device__ float g_c[ROWS];

// ---------------------------------------------------------------------------
// Fast exp on the FMA pipe (no MUFU). Valid for x <= 0 (clamped at -80).
// ---------------------------------------------------------------------------
__device__ __forceinline__ float fexp(float x) {
    x = fmaxf(x, -80.0f);
    float y = x * 1.4426950408889634f;
    float r = __fadd_rn(y, 12582912.0f);
    float n = __fadd_rn(r, -12582912.0f);
    float f = y - n;
    float p = 1.3333558e-3f;
    p = fmaf(p, f, 9.6181291e-3f);
    p = fmaf(p, f, 5.5504109e-2f);
    p = fmaf(p, f, 2.4022651e-1f);
    p = fmaf(p, f, 6.9314718e-1f);
    p = fmaf(p, f, 1.0f);
    int ei = __float_as_int(r) - 0x4B400000;
    float sc = __int_as_float((127 + ei) << 23);
    return p * sc;
}

// ---------------------------------------------------------------------------
// tf32 helpers (m16n8k8 mma.sync, fp32 accumulate)
// ---------------------------------------------------------------------------
__device__ __forceinline__ uint32_t to_tf32(float f) {
    uint32_t r;
    asm("cvt.rna.tf32.f32 %0, %1;" : "=r"(r) : "f"(f));
    return r;
}
__device__ __forceinline__ float tf32f(float f) {          // cvt, keep as float bits
    return __uint_as_float(to_tf32(f));
}

__device__ __forceinline__ void mma8(float* d, const uint32_t* a,
                                     const uint32_t* b, const float* c) {
    asm("mma.sync.aligned.m16n8k8.row.col.f32.tf32.tf32.f32 "
        "{%0,%1,%2,%3}, {%4,%5,%6,%7}, {%8,%9}, {%10,%11,%12,%13};"
        : "=f"(d[0]), "=f"(d[1]), "=f"(d[2]), "=f"(d[3])
        : "r"(a[0]), "r"(a[1]), "r"(a[2]), "r"(a[3]),
          "r"(b[0]), "r"(b[1]),
          "f"(c[0]), "f"(c[1]), "f"(c[2]), "f"(c[3]));
}

// ---------------------------------------------------------------------------
// Kernel 1: fused QKV projection via tf32 tensor cores, software-pipelined.
// C = X @ W + b, W selected by blockIdx.z. 128x64 tile, BK=32, 256 threads.
// smem holds tf32-converted data; mainloop has zero cvt instructions.
// ---------------------------------------------------------------------------
__global__ __launch_bounds__(256)
void qkv_gemm(const float* __restrict__ X,
              const float* __restrict__ Wq, const float* __restrict__ bq,
              const float* __restrict__ Wk, const float* __restrict__ bk,
              const float* __restrict__ Wv, const float* __restrict__ bv)
{
    __shared__ float Xs[128 * 36];   // [row][k], stride 36, tf32 bits
    __shared__ float Ws[32 * 72];    // [k][n],  stride 72, tf32 bits

    int z = blockIdx.z;
    const float* W    = (z == 0) ? Wq : (z == 1) ? Wk : Wv;
    const float* bias = (z == 0) ? bq : (z == 1) ? bk : bv;
    float* C = g_QKV[z];

    int row0 = blockIdx.y * 128;
    int col0 = blockIdx.x * 64;
    int tid  = threadIdx.x;
    int warp = tid >> 5, lane = tid & 31;
    int g = lane >> 2, t4 = lane & 3;
    int wm = (warp & 3) * 32;
    int wn = (warp >> 2) * 32;

    // per-thread staging coords
    int xr[4], xc[4];
    #pragma unroll
    for (int it = 0; it < 4; ++it) {
        int fi = tid + it * 256;
        xr[it] = fi >> 3; xc[it] = (fi & 7) * 4;
    }
    int wr[2], wc[2];
    #pragma unroll
    for (int it = 0; it < 2; ++it) {
        int fi = tid + it * 256;
        wr[it] = fi >> 4; wc[it] = (fi & 15) * 4;
    }

    float4 px[4], pw[2];
    #pragma unroll
    for (int it = 0; it < 4; ++it)
        px[it] = *(const float4*)(X + (size_t)(row0 + xr[it]) * DD + xc[it]);
    #pragma unroll
    for (int it = 0; it < 2; ++it)
        pw[it] = *(const float4*)(W + (size_t)wr[it] * DD + col0 + wc[it]);

    float acc[2][4][4] = {};

    for (int k0 = 0; k0 < DD; k0 += 32) {
        // store prefetched tile to smem with cvt
        #pragma unroll
        for (int it = 0; it < 4; ++it) {
            float4 v = px[it];
            float4 o = {tf32f(v.x), tf32f(v.y), tf32f(v.z), tf32f(v.w)};
            *(float4*)&Xs[xr[it] * 36 + xc[it]] = o;
        }
        #pragma unroll
        for (int it = 0; it < 2; ++it) {
            float4 v = pw[it];
            float4 o = {tf32f(v.x), tf32f(v.y), tf32f(v.z), tf32f(v.w)};
            *(float4*)&Ws[wr[it] * 72 + wc[it]] = o;
        }
        __syncthreads();

        // prefetch next tile
        if (k0 + 32 < DD) {
            #pragma unroll
            for (int it = 0; it < 4; ++it)
                px[it] = *(const float4*)(X + (size_t)(row0 + xr[it]) * DD + k0 + 32 + xc[it]);
            #pragma unroll
            for (int it = 0; it < 2; ++it)
                pw[it] = *(const float4*)(W + (size_t)(k0 + 32 + wr[it]) * DD + col0 + wc[it]);
        }

        #pragma unroll
        for (int ch = 0; ch < 4; ++ch) {
            int kk = ch * 8;
            uint32_t a[2][4];
            #pragma unroll
            for (int m = 0; m < 2; ++m) {
                int rb = wm + m * 16;
                a[m][0] = __float_as_uint(Xs[(rb + g) * 36 + kk + t4]);
                a[m][1] = __float_as_uint(Xs[(rb + g + 8) * 36 + kk + t4]);
                a[m][2] = __float_as_uint(Xs[(rb + g) * 36 + kk + t4 + 4]);
                a[m][3] = __float_as_uint(Xs[(rb + g + 8) * 36 + kk + t4 + 4]);
            }
            uint32_t bf[4][2];
            #pragma unroll
            for (int n = 0; n < 4; ++n) {
                int cb = wn + n * 8 + g;
                bf[n][0] = __float_as_uint(Ws[(kk + t4) * 72 + cb]);
                bf[n][1] = __float_as_uint(Ws[(kk + t4 + 4) * 72 + cb]);
            }
            #pragma unroll
            for (int m = 0; m < 2; ++m)
                #pragma unroll
                for (int n = 0; n < 4; ++n)
                    mma8(acc[m][n], a[m], bf[n], acc[m][n]);
        }
        __syncthreads();
    }

    #pragma unroll
    for (int n = 0; n < 4; ++n) {
        int col = col0 + wn + n * 8 + 2 * t4;
        float2 bb = *(const float2*)(bias + col);
        #pragma unroll
        for (int m = 0; m < 2; ++m) {
            int r0 = row0 + wm + m * 16 + g;
            float2 o0 = {acc[m][n][0] + bb.x, acc[m][n][1] + bb.y};
            float2 o1 = {acc[m][n][2] + bb.x, acc[m][n][3] + bb.y};
            *(float2*)(C + (size_t)r0 * DD + col) = o0;
            *(float2*)(C + (size_t)(r0 + 8) * DD + col) = o1;
        }
    }
}

// ---------------------------------------------------------------------------
// Kernel 2: c[row] = x[row] . w_g[D:2D]   (a_i + b_g cancel in softmax)
// ---------------------------------------------------------------------------
__global__ __launch_bounds__(256)
void gate_kernel(const float* __restrict__ x, const float* __restrict__ wg)
{
    int row  = blockIdx.x * 8 + (threadIdx.x >> 5);
    int lane = threadIdx.x & 31;
    const float* xr = x + (size_t)row * DD;
    const float* w2 = wg + DD;
    float s = 0.f;
    #pragma unroll 4
    for (int d = lane; d < DD; d += 32) s = fmaf(xr[d], w2[d], s);
    #pragma unroll
    for (int off = 16; off > 0; off >>= 1)
        s += __shfl_xor_sync(0xffffffffu, s, off);
    if (lane == 0) g_c[row] = s;
}

// ---------------------------------------------------------------------------
// Kernel 3: flash attention on tf32 tensor cores.
// CTA = (64-query tile, h, b), 128 threads = 4 warps x 16 query rows.
// All smem operands pre-converted to tf32: zero cvt in the mainloop.
// exp(t + log(adj+eps) - m) == (adj+eps)*exp(t - m): no logs anywhere.
// ---------------------------------------------------------------------------
__global__ __launch_bounds__(128, 4)
void attn_kernel(const float* __restrict__ x, const float* __restrict__ adj,
                 float* __restrict__ out)
{
    extern __shared__ float sm[];
    float* Ks = sm;                     // [64][68]  tf32 bits
    float* Vs = sm + 64 * 68;           // [64][72]  tf32 bits
    float* Ps = sm + 64 * 68 + 64 * 72; // [64][68]  Q staging then P, tf32 bits

    int tid  = threadIdx.x;
    int warp = tid >> 5, lane = tid & 31;
    int g = lane >> 2, t4 = lane & 3;
    int qr = warp * 16;
    int i0 = blockIdx.x * 64;
    int h  = blockIdx.y;
    int b  = blockIdx.z;

    const float* Qg = g_QKV[0] + (size_t)b * NN * DD + h * HD;
    const float* Kg = g_QKV[1] + (size_t)b * NN * DD + h * HD;
    const float* Vg = g_QKV[2] + (size_t)b * NN * DD + h * HD;
    const float* cv   = g_c + b * NN;
    const float* adjb = adj + (size_t)b * NN * NN;

    // ---- Stage Q tile (64x64) tf32 into Ps; lift A fragments to regs ----
    #pragma unroll
    for (int it = 0; it < 8; ++it) {
        int fi = tid + it * 128;
        int r = fi >> 4, c4 = (fi & 15) * 4;
        float4 v = *(const float4*)(Qg + (size_t)(i0 + r) * DD + c4);
        float4 o = {tf32f(v.x), tf32f(v.y), tf32f(v.z), tf32f(v.w)};
        *(float4*)&Ps[r * 68 + c4] = o;
    }
    __syncthreads();

    uint32_t qa[8][4];
    #pragma unroll
    for (int ch = 0; ch < 8; ++ch) {
        int kk = ch * 8;
        qa[ch][0] = __float_as_uint(Ps[(qr + g) * 68 + kk + t4]);
        qa[ch][1] = __float_as_uint(Ps[(qr + g + 8) * 68 + kk + t4]);
        qa[ch][2] = __float_as_uint(Ps[(qr + g) * 68 + kk + t4 + 4]);
        qa[ch][3] = __float_as_uint(Ps[(qr + g + 8) * 68 + kk + t4 + 4]);
    }

    float m0 = -1e30f, m1 = -1e30f, l0 = 0.f, l1 = 0.f;
    float o[8][4] = {};

    for (int jt = 0; jt < NN / 64; ++jt) {
        int j0 = jt * 64;
        __syncthreads();

        // stage K (stride 68) and V (stride 72), tf32-converted
        #pragma unroll
        for (int it = 0; it < 8; ++it) {
            int fi = tid + it * 128;
            int r = fi >> 4, c4 = (fi & 15) * 4;
            float4 k4 = *(const float4*)(Kg + (size_t)(j0 + r) * DD + c4);
            float4 ko = {tf32f(k4.x), tf32f(k4.y), tf32f(k4.z), tf32f(k4.w)};
            *(float4*)&Ks[r * 68 + c4] = ko;
            float4 v4 = *(const float4*)(Vg + (size_t)(j0 + r) * DD + c4);
            float4 vo = {tf32f(v4.x), tf32f(v4.y), tf32f(v4.z), tf32f(v4.w)};
            *(float4*)&Vs[r * 72 + c4] = vo;
        }
        __syncthreads();

        // ---- S = Q K^T : warp computes 16x64 ----
        float s[8][4] = {};
        #pragma unroll
        for (int ch = 0; ch < 8; ++ch) {
            int kk = ch * 8;
            #pragma unroll
            for (int n = 0; n < 8; ++n) {
                uint32_t bf[2];
                bf[0] = __float_as_uint(Ks[(n * 8 + g) * 68 + kk + t4]);
                bf[1] = __float_as_uint(Ks[(n * 8 + g) * 68 + kk + t4 + 4]);
                mma8(s[n], qa[ch], bf, s[n]);
            }
        }

        // ---- t = s/8 + c_j ; row max (rows live in 4-lane groups) ----
        float mt0 = -1e30f, mt1 = -1e30f;
        #pragma unroll
        for (int n = 0; n < 8; ++n) {
            float2 cc = *(const float2*)(cv + j0 + n * 8 + 2 * t4);
            s[n][0] = fmaf(s[n][0], 0.125f, cc.x);
            s[n][1] = fmaf(s[n][1], 0.125f, cc.y);
            s[n][2] = fmaf(s[n][2], 0.125f, cc.x);
            s[n][3] = fmaf(s[n][3], 0.125f, cc.y);
            mt0 = fmaxf(mt0, fmaxf(s[n][0], s[n][1]));
            mt1 = fmaxf(mt1, fmaxf(s[n][2], s[n][3]));
        }
        mt0 = fmaxf(mt0, __shfl_xor_sync(0xffffffffu, mt0, 1));
        mt0 = fmaxf(mt0, __shfl_xor_sync(0xffffffffu, mt0, 2));
        mt1 = fmaxf(mt1, __shfl_xor_sync(0xffffffffu, mt1, 1));
        mt1 = fmaxf(mt1, __shfl_xor_sync(0xffffffffu, mt1, 2));

        float m0n = fmaxf(m0, mt0), m1n = fmaxf(m1, mt1);
        float a0 = fexp(m0 - m0n), a1 = fexp(m1 - m1n);
        m0 = m0n; m1 = m1n;

        // ---- p = (adj+eps)*exp(t-m); store tf32 P; row sums ----
        float rs0 = 0.f, rs1 = 0.f;
        int r0 = i0 + qr + g, r1 = r0 + 8;
        #pragma unroll
        for (int n = 0; n < 8; ++n) {
            int jc = j0 + n * 8 + 2 * t4;
            float2 ad0 = *(const float2*)(adjb + (size_t)r0 * NN + jc);
            float2 ad1 = *(const float2*)(adjb + (size_t)r1 * NN + jc);
            float p00 = fexp(s[n][0] - m0) * (ad0.x + 1e-9f);
            float p01 = fexp(s[n][1] - m0) * (ad0.y + 1e-9f);
            float p10 = fexp(s[n][2] - m1) * (ad1.x + 1e-9f);
            float p11 = fexp(s[n][3] - m1) * (ad1.y + 1e-9f);
            rs0 += p00 + p01; rs1 += p10 + p11;
            float2 w0 = {tf32f(p00), tf32f(p01)};
            float2 w1 = {tf32f(p10), tf32f(p11)};
            *(float2*)&Ps[(qr + g) * 68 + n * 8 + 2 * t4] = w0;
            *(float2*)&Ps[(qr + g + 8) * 68 + n * 8 + 2 * t4] = w1;
        }
        rs0 += __shfl_xor_sync(0xffffffffu, rs0, 1);
        rs0 += __shfl_xor_sync(0xffffffffu, rs0, 2);
        rs1 += __shfl_xor_sync(0xffffffffu, rs1, 1);
        rs1 += __shfl_xor_sync(0xffffffffu, rs1, 2);
        l0 = l0 * a0 + rs0;
        l1 = l1 * a1 + rs1;

        #pragma unroll
        for (int n = 0; n < 8; ++n) {
            o[n][0] *= a0; o[n][1] *= a0; o[n][2] *= a1; o[n][3] *= a1;
        }
        __syncwarp();   // P rows are warp-private

        // ---- O += P @ V ----
        #pragma unroll
        for (int ch = 0; ch < 8; ++ch) {
            int kk = ch * 8;
            uint32_t pa[4];
            pa[0] = __float_as_uint(Ps[(qr + g) * 68 + kk + t4]);
            pa[1] = __float_as_uint(Ps[(qr + g + 8) * 68 + kk + t4]);
            pa[2] = __float_as_uint(Ps[(qr + g) * 68 + kk + t4 + 4]);
            pa[3] = __float_as_uint(Ps[(qr + g + 8) * 68 + kk + t4 + 4]);
            #pragma unroll
            for (int n = 0; n < 8; ++n) {
                uint32_t bf[2];
                bf[0] = __float_as_uint(Vs[(kk + t4) * 72 + n * 8 + g]);
                bf[1] = __float_as_uint(Vs[(kk + t4 + 4) * 72 + n * 8 + g]);
                mma8(o[n], pa, bf, o[n]);
            }
        }
    }

    // ---- epilogue: normalize + residual ----
    float inv0 = __fdividef(1.0f, l0);
    float inv1 = __fdividef(1.0f, l1);
    int r0 = i0 + qr + g, r1 = r0 + 8;
    #pragma unroll
    for (int n = 0; n < 8; ++n) {
        int col = h * HD + n * 8 + 2 * t4;
        float2 x0 = *(const float2*)(x + ((size_t)b * NN + r0) * DD + col);
        float2 x1 = *(const float2*)(x + ((size_t)b * NN + r1) * DD + col);
        float2 o0 = {fmaf(o[n][0], inv0, x0.x), fmaf(o[n][1], inv0, x0.y)};
        float2 o1 = {fmaf(o[n][2], inv1, x1.x), fmaf(o[n][3], inv1, x1.y)};
        *(float2*)(out + ((size_t)b * NN + r0) * DD + col) = o0;
        *(float2*)(out + ((size_t)b * NN + r1) * DD + col) = o1;
    }
}

// ---------------------------------------------------------------------------
extern "C" void kernel_launch(void* const* d_in, const int* in_sizes, int n_in,
                              void* d_out, int out_size)
{
    const float* x   = (const float*)d_in[0];
    const float* adj = (const float*)d_in[1];
    const float* Wq  = (const float*)d_in[2];
    const float* bq  = (const float*)d_in[3];
    const float* Wk  = (const float*)d_in[4];
    const float* bk  = (const float*)d_in[5];
    const float* Wv  = (const float*)d_in[6];
    const float* bv  = (const float*)d_in[7];
    const float* wg  = (const float*)d_in[8];
    // d_in[9] (b_g) cancels inside the softmax; unused.
    float* out = (float*)d_out;

    const int attn_smem = (64 * 68 + 64 * 72 + 64 * 68) * (int)sizeof(float); // 53248
    cudaFuncSetAttribute((const void*)attn_kernel,
                         cudaFuncAttributeMaxDynamicSharedMemorySize, attn_smem);

    qkv_gemm<<<dim3(DD / 64, ROWS / 128, 3), 256>>>(x, Wq, bq, Wk, bk, Wv, bv);
    gate_kernel<<<ROWS / 8, 256>>>(x, wg);
    attn_kernel<<<dim3(NN / 64, HH, BB), 128, attn_smem>>>(x, adj, out);
}

// round 4
// speedup vs baseline: 4.1060x; 1.4115x over previous
#include <cuda_runtime.h>
#include <cuda_bf16.h>
#include <cstdint>

#define BB 2
#define NN 2048
#define DD 512
#define HH 8
#define HD 64
#define ROWS (BB*NN)

// Scratch (no allocations allowed): Q, K, V projections (bf16) + gate vector c
__device__ __nv_bfloat16 g_QKV[3][(size_t)ROWS * DD];
__device__ float g_c[ROWS];

// ---------------------------------------------------------------------------
// Fast exp on the FMA pipe (no MUFU). Valid for x <= 0 (clamped at -80).
// ---------------------------------------------------------------------------
__device__ __forceinline__ float fexp(float x) {
    x = fmaxf(x, -80.0f);
    float y = x * 1.4426950408889634f;
    float r = __fadd_rn(y, 12582912.0f);
    float n = __fadd_rn(r, -12582912.0f);
    float f = y - n;
    float p = 1.3333558e-3f;
    p = fmaf(p, f, 9.6181291e-3f);
    p = fmaf(p, f, 5.5504109e-2f);
    p = fmaf(p, f, 2.4022651e-1f);
    p = fmaf(p, f, 6.9314718e-1f);
    p = fmaf(p, f, 1.0f);
    int ei = __float_as_int(r) - 0x4B400000;
    float sc = __int_as_float((127 + ei) << 23);
    return p * sc;
}

// ---------------------------------------------------------------------------
// mma / cvt / ldmatrix helpers
// ---------------------------------------------------------------------------
__device__ __forceinline__ uint32_t to_tf32(float f) {
    uint32_t r;
    asm("cvt.rna.tf32.f32 %0, %1;" : "=r"(r) : "f"(f));
    return r;
}
__device__ __forceinline__ float tf32f(float f) {
    return __uint_as_float(to_tf32(f));
}
__device__ __forceinline__ uint32_t pack_bf16(float lo, float hi) {
    uint32_t r;
    asm("cvt.rn.bf16x2.f32 %0, %1, %2;" : "=r"(r) : "f"(hi), "f"(lo));
    return r;
}

__device__ __forceinline__ void mma8(float* d, const uint32_t* a,
                                     const uint32_t* b, const float* c) {
    asm("mma.sync.aligned.m16n8k8.row.col.f32.tf32.tf32.f32 "
        "{%0,%1,%2,%3}, {%4,%5,%6,%7}, {%8,%9}, {%10,%11,%12,%13};"
        : "=f"(d[0]), "=f"(d[1]), "=f"(d[2]), "=f"(d[3])
        : "r"(a[0]), "r"(a[1]), "r"(a[2]), "r"(a[3]),
          "r"(b[0]), "r"(b[1]),
          "f"(c[0]), "f"(c[1]), "f"(c[2]), "f"(c[3]));
}

__device__ __forceinline__ void mma16(float* d, const uint32_t* a,
                                      uint32_t b0, uint32_t b1, const float* c) {
    asm("mma.sync.aligned.m16n8k16.row.col.f32.bf16.bf16.f32 "
        "{%0,%1,%2,%3}, {%4,%5,%6,%7}, {%8,%9}, {%10,%11,%12,%13};"
        : "=f"(d[0]), "=f"(d[1]), "=f"(d[2]), "=f"(d[3])
        : "r"(a[0]), "r"(a[1]), "r"(a[2]), "r"(a[3]),
          "r"(b0), "r"(b1),
          "f"(c[0]), "f"(c[1]), "f"(c[2]), "f"(c[3]));
}

__device__ __forceinline__ void ldm_x4_trans(uint32_t* r, const void* ptr) {
    uint32_t a = (uint32_t)__cvta_generic_to_shared(ptr);
    asm volatile("ldmatrix.sync.aligned.m8n8.x4.trans.shared.b16 "
                 "{%0,%1,%2,%3}, [%4];"
                 : "=r"(r[0]), "=r"(r[1]), "=r"(r[2]), "=r"(r[3]) : "r"(a));
}

// ---------------------------------------------------------------------------
// Kernel 1: fused QKV projection, tf32 tensor cores, bf16 output.
// C = bf16(X @ W + b). 128x64 tile, BK=32, 256 threads, pipelined.
// ---------------------------------------------------------------------------
__global__ __launch_bounds__(256)
void qkv_gemm(const float* __restrict__ X,
              const float* __restrict__ Wq, const float* __restrict__ bq,
              const float* __restrict__ Wk, const float* __restrict__ bk,
              const float* __restrict__ Wv, const float* __restrict__ bv)
{
    __shared__ float Xs[128 * 36];
    __shared__ float Ws[32 * 72];

    int z = blockIdx.z;
    const float* W    = (z == 0) ? Wq : (z == 1) ? Wk : Wv;
    const float* bias = (z == 0) ? bq : (z == 1) ? bk : bv;
    __nv_bfloat16* C = g_QKV[z];

    int row0 = blockIdx.y * 128;
    int col0 = blockIdx.x * 64;
    int tid  = threadIdx.x;
    int warp = tid >> 5, lane = tid & 31;
    int g = lane >> 2, t4 = lane & 3;
    int wm = (warp & 3) * 32;
    int wn = (warp >> 2) * 32;

    int xr[4], xc[4];
    #pragma unroll
    for (int it = 0; it < 4; ++it) {
        int fi = tid + it * 256;
        xr[it] = fi >> 3; xc[it] = (fi & 7) * 4;
    }
    int wr[2], wc[2];
    #pragma unroll
    for (int it = 0; it < 2; ++it) {
        int fi = tid + it * 256;
        wr[it] = fi >> 4; wc[it] = (fi & 15) * 4;
    }

    float4 px[4], pw[2];
    #pragma unroll
    for (int it = 0; it < 4; ++it)
        px[it] = *(const float4*)(X + (size_t)(row0 + xr[it]) * DD + xc[it]);
    #pragma unroll
    for (int it = 0; it < 2; ++it)
        pw[it] = *(const float4*)(W + (size_t)wr[it] * DD + col0 + wc[it]);

    float acc[2][4][4] = {};

    for (int k0 = 0; k0 < DD; k0 += 32) {
        #pragma unroll
        for (int it = 0; it < 4; ++it) {
            float4 v = px[it];
            float4 o = {tf32f(v.x), tf32f(v.y), tf32f(v.z), tf32f(v.w)};
            *(float4*)&Xs[xr[it] * 36 + xc[it]] = o;
        }
        #pragma unroll
        for (int it = 0; it < 2; ++it) {
            float4 v = pw[it];
            float4 o = {tf32f(v.x), tf32f(v.y), tf32f(v.z), tf32f(v.w)};
            *(float4*)&Ws[wr[it] * 72 + wc[it]] = o;
        }
        __syncthreads();

        if (k0 + 32 < DD) {
            #pragma unroll
            for (int it = 0; it < 4; ++it)
                px[it] = *(const float4*)(X + (size_t)(row0 + xr[it]) * DD + k0 + 32 + xc[it]);
            #pragma unroll
            for (int it = 0; it < 2; ++it)
                pw[it] = *(const float4*)(W + (size_t)(k0 + 32 + wr[it]) * DD + col0 + wc[it]);
        }

        #pragma unroll
        for (int ch = 0; ch < 4; ++ch) {
            int kk = ch * 8;
            uint32_t a[2][4];
            #pragma unroll
            for (int m = 0; m < 2; ++m) {
                int rb = wm + m * 16;
                a[m][0] = __float_as_uint(Xs[(rb + g) * 36 + kk + t4]);
                a[m][1] = __float_as_uint(Xs[(rb + g + 8) * 36 + kk + t4]);
                a[m][2] = __float_as_uint(Xs[(rb + g) * 36 + kk + t4 + 4]);
                a[m][3] = __float_as_uint(Xs[(rb + g + 8) * 36 + kk + t4 + 4]);
            }
            uint32_t bf[4][2];
            #pragma unroll
            for (int n = 0; n < 4; ++n) {
                int cb = wn + n * 8 + g;
                bf[n][0] = __float_as_uint(Ws[(kk + t4) * 72 + cb]);
                bf[n][1] = __float_as_uint(Ws[(kk + t4 + 4) * 72 + cb]);
            }
            #pragma unroll
            for (int m = 0; m < 2; ++m)
                #pragma unroll
                for (int n = 0; n < 4; ++n)
                    mma8(acc[m][n], a[m], bf[n], acc[m][n]);
        }
        __syncthreads();
    }

    // epilogue: + bias, pack to bf16
    #pragma unroll
    for (int n = 0; n < 4; ++n) {
        int col = col0 + wn + n * 8 + 2 * t4;
        float2 bb = *(const float2*)(bias + col);
        #pragma unroll
        for (int m = 0; m < 2; ++m) {
            int r0 = row0 + wm + m * 16 + g;
            *(uint32_t*)(C + (size_t)r0 * DD + col) =
                pack_bf16(acc[m][n][0] + bb.x, acc[m][n][1] + bb.y);
            *(uint32_t*)(C + (size_t)(r0 + 8) * DD + col) =
                pack_bf16(acc[m][n][2] + bb.x, acc[m][n][3] + bb.y);
        }
    }
}

// ---------------------------------------------------------------------------
// Kernel 2: c[row] = x[row] . w_g[D:2D]   (a_i + b_g cancel in softmax)
// ---------------------------------------------------------------------------
__global__ __launch_bounds__(256)
void gate_kernel(const float* __restrict__ x, const float* __restrict__ wg)
{
    int row  = blockIdx.x * 8 + (threadIdx.x >> 5);
    int lane = threadIdx.x & 31;
    const float* xr = x + (size_t)row * DD;
    const float* w2 = wg + DD;
    float s = 0.f;
    #pragma unroll 4
    for (int d = lane; d < DD; d += 32) s = fmaf(xr[d], w2[d], s);
    #pragma unroll
    for (int off = 16; off > 0; off >>= 1)
        s += __shfl_xor_sync(0xffffffffu, s, off);
    if (lane == 0) g_c[row] = s;
}

// ---------------------------------------------------------------------------
// Kernel 3: flash attention on bf16 tensor cores (m16n8k16, fp32 accum).
// CTA = (64-query tile, h, b), 128 threads = 4 warps x 16 query rows.
// K/Q/P fragments: scalar uint32 LDS (conflict-free, stride 72 bf16).
// V fragments: ldmatrix.x4.trans on naturally-stored V.
// exp(t + log(adj+eps) - m) == (adj+eps)*exp(t - m): no logs anywhere.
// ---------------------------------------------------------------------------
__global__ __launch_bounds__(128, 4)
void attn_kernel(const float* __restrict__ x, const float* __restrict__ adj,
                 float* __restrict__ out)
{
    __shared__ __nv_bfloat16 Ks[64 * 72];
    __shared__ __nv_bfloat16 Vs[64 * 72];
    __shared__ __nv_bfloat16 Ps[64 * 72];   // Q staging, then P

    int tid  = threadIdx.x;
    int warp = tid >> 5, lane = tid & 31;
    int g = lane >> 2, t4 = lane & 3;
    int qr = warp * 16;
    int i0 = blockIdx.x * 64;
    int h  = blockIdx.y;
    int b  = blockIdx.z;

    const __nv_bfloat16* Qg = g_QKV[0] + (size_t)b * NN * DD + h * HD;
    const __nv_bfloat16* Kg = g_QKV[1] + (size_t)b * NN * DD + h * HD;
    const __nv_bfloat16* Vg = g_QKV[2] + (size_t)b * NN * DD + h * HD;
    const float* cv   = g_c + b * NN;
    const float* adjb = adj + (size_t)b * NN * NN;

    // ---- Stage Q tile (64x64 bf16) into Ps; lift A fragments ----
    #pragma unroll
    for (int it = 0; it < 4; ++it) {
        int fi = tid + it * 128;
        int r = fi >> 3, c8 = (fi & 7) * 8;
        uint4 v = *(const uint4*)(Qg + (size_t)(i0 + r) * DD + c8);
        *(uint4*)&Ps[r * 72 + c8] = v;
    }
    __syncthreads();

    uint32_t qa[4][4];
    #pragma unroll
    for (int ch = 0; ch < 4; ++ch) {
        int kk = ch * 16;
        qa[ch][0] = *(const uint32_t*)&Ps[(qr + g) * 72 + kk + 2 * t4];
        qa[ch][1] = *(const uint32_t*)&Ps[(qr + g + 8) * 72 + kk + 2 * t4];
        qa[ch][2] = *(const uint32_t*)&Ps[(qr + g) * 72 + kk + 8 + 2 * t4];
        qa[ch][3] = *(const uint32_t*)&Ps[(qr + g + 8) * 72 + kk + 8 + 2 * t4];
    }

    float m0 = -1e30f, m1 = -1e30f, l0 = 0.f, l1 = 0.f;
    float o[8][4] = {};

    // ldmatrix source rows/cols for V (per lane, fixed across chunks)
    int lrow = (lane & 7) + 8 * ((lane >> 3) & 1);
    int lsel = lane >> 4;   // 0: n-tile 2np, 1: n-tile 2np+1

    for (int jt = 0; jt < NN / 64; ++jt) {
        int j0 = jt * 64;
        __syncthreads();

        // stage K and V (bf16, natural layout, stride 72)
        #pragma unroll
        for (int it = 0; it < 4; ++it) {
            int fi = tid + it * 128;
            int r = fi >> 3, c8 = (fi & 7) * 8;
            uint4 k4 = *(const uint4*)(Kg + (size_t)(j0 + r) * DD + c8);
            *(uint4*)&Ks[r * 72 + c8] = k4;
            uint4 v4 = *(const uint4*)(Vg + (size_t)(j0 + r) * DD + c8);
            *(uint4*)&Vs[r * 72 + c8] = v4;
        }
        __syncthreads();

        // ---- S = Q K^T : warp computes 16x64 ----
        float s[8][4] = {};
        #pragma unroll
        for (int ch = 0; ch < 4; ++ch) {
            int kk = ch * 16;
            #pragma unroll
            for (int n = 0; n < 8; ++n) {
                uint32_t b0 = *(const uint32_t*)&Ks[(n * 8 + g) * 72 + kk + 2 * t4];
                uint32_t b1 = *(const uint32_t*)&Ks[(n * 8 + g) * 72 + kk + 8 + 2 * t4];
                mma16(s[n], qa[ch], b0, b1, s[n]);
            }
        }

        // ---- t = s/8 + c_j ; row max (rows live in 4-lane groups) ----
        float mt0 = -1e30f, mt1 = -1e30f;
        #pragma unroll
        for (int n = 0; n < 8; ++n) {
            float2 cc = *(const float2*)(cv + j0 + n * 8 + 2 * t4);
            s[n][0] = fmaf(s[n][0], 0.125f, cc.x);
            s[n][1] = fmaf(s[n][1], 0.125f, cc.y);
            s[n][2] = fmaf(s[n][2], 0.125f, cc.x);
            s[n][3] = fmaf(s[n][3], 0.125f, cc.y);
            mt0 = fmaxf(mt0, fmaxf(s[n][0], s[n][1]));
            mt1 = fmaxf(mt1, fmaxf(s[n][2], s[n][3]));
        }
        mt0 = fmaxf(mt0, __shfl_xor_sync(0xffffffffu, mt0, 1));
        mt0 = fmaxf(mt0, __shfl_xor_sync(0xffffffffu, mt0, 2));
        mt1 = fmaxf(mt1, __shfl_xor_sync(0xffffffffu, mt1, 1));
        mt1 = fmaxf(mt1, __shfl_xor_sync(0xffffffffu, mt1, 2));

        float m0n = fmaxf(m0, mt0), m1n = fmaxf(m1, mt1);
        float a0 = fexp(m0 - m0n), a1 = fexp(m1 - m1n);
        m0 = m0n; m1 = m1n;

        // ---- p = (adj+eps)*exp(t-m); store bf16 P; row sums ----
        float rs0 = 0.f, rs1 = 0.f;
        int r0 = i0 + qr + g, r1 = r0 + 8;
        #pragma unroll
        for (int n = 0; n < 8; ++n) {
            int jc = j0 + n * 8 + 2 * t4;
            float2 ad0 = *(const float2*)(adjb + (size_t)r0 * NN + jc);
            float2 ad1 = *(const float2*)(adjb + (size_t)r1 * NN + jc);
            float p00 = fexp(s[n][0] - m0) * (ad0.x + 1e-9f);
            float p01 = fexp(s[n][1] - m0) * (ad0.y + 1e-9f);
            float p10 = fexp(s[n][2] - m1) * (ad1.x + 1e-9f);
            float p11 = fexp(s[n][3] - m1) * (ad1.y + 1e-9f);
            rs0 += p00 + p01; rs1 += p10 + p11;
            *(uint32_t*)&Ps[(qr + g) * 72 + n * 8 + 2 * t4]     = pack_bf16(p00, p01);
            *(uint32_t*)&Ps[(qr + g + 8) * 72 + n * 8 + 2 * t4] = pack_bf16(p10, p11);
        }
        rs0 += __shfl_xor_sync(0xffffffffu, rs0, 1);
        rs0 += __shfl_xor_sync(0xffffffffu, rs0, 2);
        rs1 += __shfl_xor_sync(0xffffffffu, rs1, 1);
        rs1 += __shfl_xor_sync(0xffffffffu, rs1, 2);
        l0 = l0 * a0 + rs0;
        l1 = l1 * a1 + rs1;

        #pragma unroll
        for (int n = 0; n < 8; ++n) {
            o[n][0] *= a0; o[n][1] *= a0; o[n][2] *= a1; o[n][3] *= a1;
        }
        __syncwarp();   // P rows are warp-private

        // ---- O += P @ V ----
        #pragma unroll
        for (int ch = 0; ch < 4; ++ch) {
            int kk = ch * 16;
            uint32_t pa[4];
            pa[0] = *(const uint32_t*)&Ps[(qr + g) * 72 + kk + 2 * t4];
            pa[1] = *(const uint32_t*)&Ps[(qr + g + 8) * 72 + kk + 2 * t4];
            pa[2] = *(const uint32_t*)&Ps[(qr + g) * 72 + kk + 8 + 2 * t4];
            pa[3] = *(const uint32_t*)&Ps[(qr + g + 8) * 72 + kk + 8 + 2 * t4];
            #pragma unroll
            for (int np = 0; np < 4; ++np) {
                uint32_t vb[4];
                ldm_x4_trans(vb, &Vs[(kk + lrow) * 72 + (2 * np + lsel) * 8]);
                mma16(o[2 * np],     pa, vb[0], vb[1], o[2 * np]);
                mma16(o[2 * np + 1], pa, vb[2], vb[3], o[2 * np + 1]);
            }
        }
    }

    // ---- epilogue: normalize + residual (fp32) ----
    float inv0 = __fdividef(1.0f, l0);
    float inv1 = __fdividef(1.0f, l1);
    int r0 = i0 + qr + g, r1 = r0 + 8;
    #pragma unroll
    for (int n = 0; n < 8; ++n) {
        int col = h * HD + n * 8 + 2 * t4;
        float2 x0 = *(const float2*)(x + ((size_t)b * NN + r0) * DD + col);
        float2 x1 = *(const float2*)(x + ((size_t)b * NN + r1) * DD + col);
        float2 o0 = {fmaf(o[n][0], inv0, x0.x), fmaf(o[n][1], inv0, x0.y)};
        float2 o1 = {fmaf(o[n][2], inv1, x1.x), fmaf(o[n][3], inv1, x1.y)};
        *(float2*)(out + ((size_t)b * NN + r0) * DD + col) = o0;
        *(float2*)(out + ((size_t)b * NN + r1) * DD + col) = o1;
    }
}

// ---------------------------------------------------------------------------
extern "C" void kernel_launch(void* const* d_in, const int* in_sizes, int n_in,
                              void* d_out, int out_size)
{
    const float* x   = (const float*)d_in[0];
    const float* adj = (const float*)d_in[1];
    const float* Wq  = (const float*)d_in[2];
    const float* bq  = (const float*)d_in[3];
    const float* Wk  = (const float*)d_in[4];
    const float* bk  = (const float*)d_in[5];
    const float* Wv  = (const float*)d_in[6];
    const float* bv  = (const float*)d_in[7];
    const float* wg  = (const float*)d_in[8];
    // d_in[9] (b_g) cancels inside the softmax; unused.
    float* out = (float*)d_out;

    qkv_gemm<<<dim3(DD / 64, ROWS / 128, 3), 256>>>(x, Wq, bq, Wk, bk, Wv, bv);
    gate_kernel<<<ROWS / 8, 256>>>(x, wg);
    attn_kernel<<<dim3(NN / 64, HH, BB), 128>>>(x, adj, out);
}

// round 5
// speedup vs baseline: 4.5897x; 1.1178x over previous
#include <cuda_runtime.h>
#include <cuda_bf16.h>
#include <cstdint>

#define BB 2
#define NN 2048
#define DD 512
#define HH 8
#define HD 64
#define ROWS (BB*NN)

// Scratch (no allocations allowed): Q, K, V projections (bf16) + gate vector c
__device__ __nv_bfloat16 g_QKV[3][(size_t)ROWS * DD];
__device__ float g_c[ROWS];

// ---------------------------------------------------------------------------
// Fast exp on the FMA pipe (no MUFU). Valid for x <= 0 (clamped at -80).
// ---------------------------------------------------------------------------
__device__ __forceinline__ float fexp(float x) {
    x = fmaxf(x, -80.0f);
    float y = x * 1.4426950408889634f;
    float r = __fadd_rn(y, 12582912.0f);
    float n = __fadd_rn(r, -12582912.0f);
    float f = y - n;
    float p = 1.3333558e-3f;
    p = fmaf(p, f, 9.6181291e-3f);
    p = fmaf(p, f, 5.5504109e-2f);
    p = fmaf(p, f, 2.4022651e-1f);
    p = fmaf(p, f, 6.9314718e-1f);
    p = fmaf(p, f, 1.0f);
    int ei = __float_as_int(r) - 0x4B400000;
    float sc = __int_as_float((127 + ei) << 23);
    return p * sc;
}

// ---------------------------------------------------------------------------
// bf16 mma / cvt / ldmatrix helpers
// ---------------------------------------------------------------------------
__device__ __forceinline__ uint32_t pack_bf16(float lo, float hi) {
    uint32_t r;
    asm("cvt.rn.bf16x2.f32 %0, %1, %2;" : "=r"(r) : "f"(hi), "f"(lo));
    return r;
}

__device__ __forceinline__ void mma16(float* d, const uint32_t* a,
                                      uint32_t b0, uint32_t b1, const float* c) {
    asm("mma.sync.aligned.m16n8k16.row.col.f32.bf16.bf16.f32 "
        "{%0,%1,%2,%3}, {%4,%5,%6,%7}, {%8,%9}, {%10,%11,%12,%13};"
        : "=f"(d[0]), "=f"(d[1]), "=f"(d[2]), "=f"(d[3])
        : "r"(a[0]), "r"(a[1]), "r"(a[2]), "r"(a[3]),
          "r"(b0), "r"(b1),
          "f"(c[0]), "f"(c[1]), "f"(c[2]), "f"(c[3]));
}

__device__ __forceinline__ void ldm_x4(uint32_t* r, const void* ptr) {
    uint32_t a = (uint32_t)__cvta_generic_to_shared(ptr);
    asm volatile("ldmatrix.sync.aligned.m8n8.x4.shared.b16 "
                 "{%0,%1,%2,%3}, [%4];"
                 : "=r"(r[0]), "=r"(r[1]), "=r"(r[2]), "=r"(r[3]) : "r"(a));
}

__device__ __forceinline__ void ldm_x4_trans(uint32_t* r, const void* ptr) {
    uint32_t a = (uint32_t)__cvta_generic_to_shared(ptr);
    asm volatile("ldmatrix.sync.aligned.m8n8.x4.trans.shared.b16 "
                 "{%0,%1,%2,%3}, [%4];"
                 : "=r"(r[0]), "=r"(r[1]), "=r"(r[2]), "=r"(r[3]) : "r"(a));
}

// ---------------------------------------------------------------------------
// Kernel 1: fused QKV projection, bf16 tensor cores (m16n8k16), bf16 output.
// C = bf16(X @ W + b). 128x64 tile, BK=32, 256 threads, reg-prefetch pipeline.
// A fragments: ldmatrix x4 on Xs[row][k] (stride 40 bf16, conflict-free).
// B fragments: ldmatrix x4.trans on Ws[k][n] (stride 72 bf16, conflict-free).
// ---------------------------------------------------------------------------
__global__ __launch_bounds__(256)
void qkv_gemm(const float* __restrict__ X,
              const float* __restrict__ Wq, const float* __restrict__ bq,
              const float* __restrict__ Wk, const float* __restrict__ bk,
              const float* __restrict__ Wv, const float* __restrict__ bv)
{
    __shared__ __nv_bfloat16 Xs[128 * 40];
    __shared__ __nv_bfloat16 Ws[32 * 72];

    int z = blockIdx.z;
    const float* W    = (z == 0) ? Wq : (z == 1) ? Wk : Wv;
    const float* bias = (z == 0) ? bq : (z == 1) ? bk : bv;
    __nv_bfloat16* C = g_QKV[z];

    int row0 = blockIdx.y * 128;
    int col0 = blockIdx.x * 64;
    int tid  = threadIdx.x;
    int warp = tid >> 5, lane = tid & 31;
    int g = lane >> 2, t4 = lane & 3;
    int wm = (warp & 3) * 32;
    int wn = (warp >> 2) * 32;

    // ldmatrix lane constants
    int a_r = ((lane >> 3) & 1) * 8 + (lane & 7);   // A (non-trans) row
    int a_c = (lane >> 4) * 8;                      //   col offset
    int v_r = (lane & 7) + ((lane >> 3) & 1) * 8;   // B (trans) row
    int v_s = lane >> 4;                            //   col-tile select

    // staging coords: X 128x32 (16 elems/thread), W 32x64 (8 elems/thread)
    int xrr[2], xcc[2];
    #pragma unroll
    for (int it = 0; it < 2; ++it) {
        int fi = tid + it * 256;
        xrr[it] = fi >> 2; xcc[it] = (fi & 3) * 8;
    }
    int wrr = tid >> 3, wcc = (tid & 7) * 8;

    float4 px[2][2], pw[2];
    #pragma unroll
    for (int it = 0; it < 2; ++it) {
        px[it][0] = *(const float4*)(X + (size_t)(row0 + xrr[it]) * DD + xcc[it]);
        px[it][1] = *(const float4*)(X + (size_t)(row0 + xrr[it]) * DD + xcc[it] + 4);
    }
    pw[0] = *(const float4*)(W + (size_t)wrr * DD + col0 + wcc);
    pw[1] = *(const float4*)(W + (size_t)wrr * DD + col0 + wcc + 4);

    float acc[2][4][4] = {};

    for (int k0 = 0; k0 < DD; k0 += 32) {
        // store staged tiles (pack fp32 -> bf16x2)
        #pragma unroll
        for (int it = 0; it < 2; ++it) {
            uint4 u;
            u.x = pack_bf16(px[it][0].x, px[it][0].y);
            u.y = pack_bf16(px[it][0].z, px[it][0].w);
            u.z = pack_bf16(px[it][1].x, px[it][1].y);
            u.w = pack_bf16(px[it][1].z, px[it][1].w);
            *(uint4*)&Xs[xrr[it] * 40 + xcc[it]] = u;
        }
        {
            uint4 u;
            u.x = pack_bf16(pw[0].x, pw[0].y);
            u.y = pack_bf16(pw[0].z, pw[0].w);
            u.z = pack_bf16(pw[1].x, pw[1].y);
            u.w = pack_bf16(pw[1].z, pw[1].w);
            *(uint4*)&Ws[wrr * 72 + wcc] = u;
        }
        __syncthreads();

        if (k0 + 32 < DD) {
            #pragma unroll
            for (int it = 0; it < 2; ++it) {
                px[it][0] = *(const float4*)(X + (size_t)(row0 + xrr[it]) * DD + k0 + 32 + xcc[it]);
                px[it][1] = *(const float4*)(X + (size_t)(row0 + xrr[it]) * DD + k0 + 32 + xcc[it] + 4);
            }
            pw[0] = *(const float4*)(W + (size_t)(k0 + 32 + wrr) * DD + col0 + wcc);
            pw[1] = *(const float4*)(W + (size_t)(k0 + 32 + wrr) * DD + col0 + wcc + 4);
        }

        #pragma unroll
        for (int ch = 0; ch < 2; ++ch) {
            int kk = ch * 16;
            uint32_t a[2][4];
            ldm_x4(a[0], &Xs[(wm + a_r) * 40 + kk + a_c]);
            ldm_x4(a[1], &Xs[(wm + 16 + a_r) * 40 + kk + a_c]);
            uint32_t bqf[2][4];
            ldm_x4_trans(bqf[0], &Ws[(kk + v_r) * 72 + wn + v_s * 8]);
            ldm_x4_trans(bqf[1], &Ws[(kk + v_r) * 72 + wn + 16 + v_s * 8]);
            #pragma unroll
            for (int m = 0; m < 2; ++m) {
                mma16(acc[m][0], a[m], bqf[0][0], bqf[0][1], acc[m][0]);
                mma16(acc[m][1], a[m], bqf[0][2], bqf[0][3], acc[m][1]);
                mma16(acc[m][2], a[m], bqf[1][0], bqf[1][1], acc[m][2]);
                mma16(acc[m][3], a[m], bqf[1][2], bqf[1][3], acc[m][3]);
            }
        }
        __syncthreads();
    }

    // epilogue: + bias, pack to bf16
    #pragma unroll
    for (int n = 0; n < 4; ++n) {
        int col = col0 + wn + n * 8 + 2 * t4;
        float2 bb = *(const float2*)(bias + col);
        #pragma unroll
        for (int m = 0; m < 2; ++m) {
            int r0 = row0 + wm + m * 16 + g;
            *(uint32_t*)(C + (size_t)r0 * DD + col) =
                pack_bf16(acc[m][n][0] + bb.x, acc[m][n][1] + bb.y);
            *(uint32_t*)(C + (size_t)(r0 + 8) * DD + col) =
                pack_bf16(acc[m][n][2] + bb.x, acc[m][n][3] + bb.y);
        }
    }
}

// ---------------------------------------------------------------------------
// Kernel 2: c[row] = x[row] . w_g[D:2D]   (a_i + b_g cancel in softmax)
// ---------------------------------------------------------------------------
__global__ __launch_bounds__(256)
void gate_kernel(const float* __restrict__ x, const float* __restrict__ wg)
{
    int row  = blockIdx.x * 8 + (threadIdx.x >> 5);
    int lane = threadIdx.x & 31;
    const float* xr = x + (size_t)row * DD;
    const float* w2 = wg + DD;
    float s = 0.f;
    #pragma unroll 4
    for (int d = lane; d < DD; d += 32) s = fmaf(xr[d], w2[d], s);
    #pragma unroll
    for (int off = 16; off > 0; off >>= 1)
        s += __shfl_xor_sync(0xffffffffu, s, off);
    if (lane == 0) g_c[row] = s;
}

// ---------------------------------------------------------------------------
// Kernel 3: flash attention on bf16 tensor cores (m16n8k16, fp32 accum).
// CTA = (64-query tile, h, b), 128 threads = 4 warps x 16 query rows.
// All fragments via ldmatrix.x4 (Q/P: non-trans A; K: non-trans B; V: trans B).
// exp(t + log(adj+eps) - m) == (adj+eps)*exp(t - m): no logs anywhere.
// ---------------------------------------------------------------------------
__global__ __launch_bounds__(128, 4)
void attn_kernel(const float* __restrict__ x, const float* __restrict__ adj,
                 float* __restrict__ out)
{
    __shared__ __nv_bfloat16 Ks[64 * 72];
    __shared__ __nv_bfloat16 Vs[64 * 72];
    __shared__ __nv_bfloat16 Ps[64 * 72];   // Q staging, then P

    int tid  = threadIdx.x;
    int warp = tid >> 5, lane = tid & 31;
    int g = lane >> 2, t4 = lane & 3;
    int qr = warp * 16;
    int i0 = blockIdx.x * 64;
    int h  = blockIdx.y;
    int b  = blockIdx.z;

    // ldmatrix lane constants
    int a_r = ((lane >> 3) & 1) * 8 + (lane & 7);   // A (non-trans: Q, P)
    int a_c = (lane >> 4) * 8;
    int k_r = (lane >> 4) * 8 + (lane & 7);         // B non-trans (K rows = n)
    int k_c = ((lane >> 3) & 1) * 8;
    int v_r = (lane & 7) + ((lane >> 3) & 1) * 8;   // B trans (V, rows = k)
    int v_s = lane >> 4;

    const __nv_bfloat16* Qg = g_QKV[0] + (size_t)b * NN * DD + h * HD;
    const __nv_bfloat16* Kg = g_QKV[1] + (size_t)b * NN * DD + h * HD;
    const __nv_bfloat16* Vg = g_QKV[2] + (size_t)b * NN * DD + h * HD;
    const float* cv   = g_c + b * NN;
    const float* adjb = adj + (size_t)b * NN * NN;

    // ---- Stage Q tile (64x64 bf16) into Ps; lift A fragments ----
    #pragma unroll
    for (int it = 0; it < 4; ++it) {
        int fi = tid + it * 128;
        int r = fi >> 3, c8 = (fi & 7) * 8;
        uint4 v = *(const uint4*)(Qg + (size_t)(i0 + r) * DD + c8);
        *(uint4*)&Ps[r * 72 + c8] = v;
    }
    __syncthreads();

    uint32_t qa[4][4];
    #pragma unroll
    for (int ch = 0; ch < 4; ++ch)
        ldm_x4(qa[ch], &Ps[(qr + a_r) * 72 + ch * 16 + a_c]);

    float m0 = -1e30f, m1 = -1e30f, l0 = 0.f, l1 = 0.f;
    float o[8][4] = {};

    for (int jt = 0; jt < NN / 64; ++jt) {
        int j0 = jt * 64;
        __syncthreads();

        // stage K and V (bf16, natural layout, stride 72)
        #pragma unroll
        for (int it = 0; it < 4; ++it) {
            int fi = tid + it * 128;
            int r = fi >> 3, c8 = (fi & 7) * 8;
            uint4 k4 = *(const uint4*)(Kg + (size_t)(j0 + r) * DD + c8);
            *(uint4*)&Ks[r * 72 + c8] = k4;
            uint4 v4 = *(const uint4*)(Vg + (size_t)(j0 + r) * DD + c8);
            *(uint4*)&Vs[r * 72 + c8] = v4;
        }
        __syncthreads();

        // ---- S = Q K^T : warp computes 16x64 ----
        float s[8][4] = {};
        #pragma unroll
        for (int ch = 0; ch < 4; ++ch) {
            int kk = ch * 16;
            #pragma unroll
            for (int np = 0; np < 4; ++np) {
                uint32_t kb[4];
                ldm_x4(kb, &Ks[(np * 16 + k_r) * 72 + kk + k_c]);
                mma16(s[2 * np],     qa[ch], kb[0], kb[1], s[2 * np]);
                mma16(s[2 * np + 1], qa[ch], kb[2], kb[3], s[2 * np + 1]);
            }
        }

        // ---- t = s/8 + c_j ; row max (rows live in 4-lane groups) ----
        float mt0 = -1e30f, mt1 = -1e30f;
        #pragma unroll
        for (int n = 0; n < 8; ++n) {
            float2 cc = *(const float2*)(cv + j0 + n * 8 + 2 * t4);
            s[n][0] = fmaf(s[n][0], 0.125f, cc.x);
            s[n][1] = fmaf(s[n][1], 0.125f, cc.y);
            s[n][2] = fmaf(s[n][2], 0.125f, cc.x);
            s[n][3] = fmaf(s[n][3], 0.125f, cc.y);
            mt0 = fmaxf(mt0, fmaxf(s[n][0], s[n][1]));
            mt1 = fmaxf(mt1, fmaxf(s[n][2], s[n][3]));
        }
        mt0 = fmaxf(mt0, __shfl_xor_sync(0xffffffffu, mt0, 1));
        mt0 = fmaxf(mt0, __shfl_xor_sync(0xffffffffu, mt0, 2));
        mt1 = fmaxf(mt1, __shfl_xor_sync(0xffffffffu, mt1, 1));
        mt1 = fmaxf(mt1, __shfl_xor_sync(0xffffffffu, mt1, 2));

        float m0n = fmaxf(m0, mt0), m1n = fmaxf(m1, mt1);
        float a0 = fexp(m0 - m0n), a1 = fexp(m1 - m1n);
        m0 = m0n; m1 = m1n;

        // ---- p = (adj+eps)*exp(t-m); store bf16 P; row sums ----
        float rs0 = 0.f, rs1 = 0.f;
        int r0 = i0 + qr + g, r1 = r0 + 8;
        #pragma unroll
        for (int n = 0; n < 8; ++n) {
            int jc = j0 + n * 8 + 2 * t4;
            float2 ad0 = *(const float2*)(adjb + (size_t)r0 * NN + jc);
            float2 ad1 = *(const float2*)(adjb + (size_t)r1 * NN + jc);
            float p00 = fexp(s[n][0] - m0) * (ad0.x + 1e-9f);
            float p01 = fexp(s[n][1] - m0) * (ad0.y + 1e-9f);
            float p10 = fexp(s[n][2] - m1) * (ad1.x + 1e-9f);
            float p11 = fexp(s[n][3] - m1) * (ad1.y + 1e-9f);
            rs0 += p00 + p01; rs1 += p10 + p11;
            *(uint32_t*)&Ps[(qr + g) * 72 + n * 8 + 2 * t4]     = pack_bf16(p00, p01);
            *(uint32_t*)&Ps[(qr + g + 8) * 72 + n * 8 + 2 * t4] = pack_bf16(p10, p11);
        }
        rs0 += __shfl_xor_sync(0xffffffffu, rs0, 1);
        rs0 += __shfl_xor_sync(0xffffffffu, rs0, 2);
        rs1 += __shfl_xor_sync(0xffffffffu, rs1, 1);
        rs1 += __shfl_xor_sync(0xffffffffu, rs1, 2);
        l0 = l0 * a0 + rs0;
        l1 = l1 * a1 + rs1;

        #pragma unroll
        for (int n = 0; n < 8; ++n) {
            o[n][0] *= a0; o[n][1] *= a0; o[n][2] *= a1; o[n][3] *= a1;
        }
        __syncwarp();   // P rows are warp-private

        // ---- O += P @ V ----
        #pragma unroll
        for (int ch = 0; ch < 4; ++ch) {
            int kk = ch * 16;
            uint32_t pa[4];
            ldm_x4(pa, &Ps[(qr + a_r) * 72 + kk + a_c]);
            #pragma unroll
            for (int np = 0; np < 4; ++np) {
                uint32_t vb[4];
                ldm_x4_trans(vb, &Vs[(kk + v_r) * 72 + (2 * np + v_s) * 8]);
                mma16(o[2 * np],     pa, vb[0], vb[1], o[2 * np]);
                mma16(o[2 * np + 1], pa, vb[2], vb[3], o[2 * np + 1]);
            }
        }
    }

    // ---- epilogue: normalize + residual (fp32) ----
    float inv0 = __fdividef(1.0f, l0);
    float inv1 = __fdividef(1.0f, l1);
    int r0 = i0 + qr + g, r1 = r0 + 8;
    #pragma unroll
    for (int n = 0; n < 8; ++n) {
        int col = h * HD + n * 8 + 2 * t4;
        float2 x0 = *(const float2*)(x + ((size_t)b * NN + r0) * DD + col);
        float2 x1 = *(const float2*)(x + ((size_t)b * NN + r1) * DD + col);
        float2 o0 = {fmaf(o[n][0], inv0, x0.x), fmaf(o[n][1], inv0, x0.y)};
        float2 o1 = {fmaf(o[n][2], inv1, x1.x), fmaf(o[n][3], inv1, x1.y)};
        *(float2*)(out + ((size_t)b * NN + r0) * DD + col) = o0;
        *(float2*)(out + ((size_t)b * NN + r1) * DD + col) = o1;
    }
}

// ---------------------------------------------------------------------------
extern "C" void kernel_launch(void* const* d_in, const int* in_sizes, int n_in,
                              void* d_out, int out_size)
{
    const float* x   = (const float*)d_in[0];
    const float* adj = (const float*)d_in[1];
    const float* Wq  = (const float*)d_in[2];
    const float* bq  = (const float*)d_in[3];
    const float* Wk  = (const float*)d_in[4];
    const float* bk  = (const float*)d_in[5];
    const float* Wv  = (const float*)d_in[6];
    const float* bv  = (const float*)d_in[7];
    const float* wg  = (const float*)d_in[8];
    // d_in[9] (b_g) cancels inside the softmax; unused.
    float* out = (float*)d_out;

    qkv_gemm<<<dim3(DD / 64, ROWS / 128, 3), 256>>>(x, Wq, bq, Wk, bk, Wv, bv);
    gate_kernel<<<ROWS / 8, 256>>>(x, wg);
    attn_kernel<<<dim3(NN / 64, HH, BB), 128>>>(x, adj, out);
}

// round 6
// speedup vs baseline: 5.4871x; 1.1955x over previous
#include <cuda_runtime.h>
#include <cuda_bf16.h>
#include <cstdint>

#define BB 2
#define NN 2048
#define DD 512
#define HH 8
#define HD 64
#define ROWS (BB*NN)

// Scratch (no allocations allowed)
__device__ __nv_bfloat16 g_QKV[3][(size_t)ROWS * DD];   // Q,K,V projections
__device__ __nv_bfloat16 g_Xb[(size_t)ROWS * DD];       // x in bf16
__device__ __nv_bfloat16 g_Wb[3][(size_t)DD * DD];      // W_q/k/v in bf16
__device__ float g_c[ROWS];                             // gate vec (pre-scaled by log2e)

#define LOG2E 1.4426950408889634f

// ---------------------------------------------------------------------------
// helpers
// ---------------------------------------------------------------------------
__device__ __forceinline__ float ex2f(float x) {        // 2^x on MUFU
    float r;
    asm("ex2.approx.f32 %0, %1;" : "=f"(r) : "f"(x));
    return r;
}
__device__ __forceinline__ uint32_t pack_bf16(float lo, float hi) {
    uint32_t r;
    asm("cvt.rn.bf16x2.f32 %0, %1, %2;" : "=r"(r) : "f"(hi), "f"(lo));
    return r;
}
__device__ __forceinline__ void mma16(float* d, const uint32_t* a,
                                      uint32_t b0, uint32_t b1, const float* c) {
    asm("mma.sync.aligned.m16n8k16.row.col.f32.bf16.bf16.f32 "
        "{%0,%1,%2,%3}, {%4,%5,%6,%7}, {%8,%9}, {%10,%11,%12,%13};"
        : "=f"(d[0]), "=f"(d[1]), "=f"(d[2]), "=f"(d[3])
        : "r"(a[0]), "r"(a[1]), "r"(a[2]), "r"(a[3]),
          "r"(b0), "r"(b1),
          "f"(c[0]), "f"(c[1]), "f"(c[2]), "f"(c[3]));
}
__device__ __forceinline__ void ldm_x4(uint32_t* r, const void* ptr) {
    uint32_t a = (uint32_t)__cvta_generic_to_shared(ptr);
    asm volatile("ldmatrix.sync.aligned.m8n8.x4.shared.b16 "
                 "{%0,%1,%2,%3}, [%4];"
                 : "=r"(r[0]), "=r"(r[1]), "=r"(r[2]), "=r"(r[3]) : "r"(a));
}
__device__ __forceinline__ void ldm_x4_trans(uint32_t* r, const void* ptr) {
    uint32_t a = (uint32_t)__cvta_generic_to_shared(ptr);
    asm volatile("ldmatrix.sync.aligned.m8n8.x4.trans.shared.b16 "
                 "{%0,%1,%2,%3}, [%4];"
                 : "=r"(r[0]), "=r"(r[1]), "=r"(r[2]), "=r"(r[3]) : "r"(a));
}
__device__ __forceinline__ void cpa16(void* smem_dst, const void* gsrc) {
    uint32_t d = (uint32_t)__cvta_generic_to_shared(smem_dst);
    asm volatile("cp.async.cg.shared.global [%0], [%1], 16;" :: "r"(d), "l"(gsrc));
}
#define CP_COMMIT asm volatile("cp.async.commit_group;" ::: "memory")
#define CP_WAIT1  asm volatile("cp.async.wait_group 1;" ::: "memory")
#define CP_WAIT0  asm volatile("cp.async.wait_group 0;" ::: "memory")

// ---------------------------------------------------------------------------
// Kernel 0: one-shot fp32 -> bf16 conversion of x and W_q/k/v.
// 8 elements per thread; 1408 blocks x 256 threads covers all 2883584 elems.
// ---------------------------------------------------------------------------
__global__ __launch_bounds__(256)
void convert_kernel(const float* __restrict__ X, const float* __restrict__ Wq,
                    const float* __restrict__ Wk, const float* __restrict__ Wv)
{
    int idx = blockIdx.x * 256 + threadIdx.x;
    const float* src;
    __nv_bfloat16* dst;
    size_t off;
    if (idx < 262144) {                       // X: 2097152 elems / 8
        src = X; dst = g_Xb; off = (size_t)idx * 8;
    } else {
        int r = idx - 262144;
        int z = r >> 15;                      // 32768 chunks per W
        int o = r & 32767;
        src = (z == 0) ? Wq : (z == 1) ? Wk : Wv;
        dst = g_Wb[z]; off = (size_t)o * 8;
    }
    float4 v0 = *(const float4*)(src + off);
    float4 v1 = *(const float4*)(src + off + 4);
    uint4 u;
    u.x = pack_bf16(v0.x, v0.y);
    u.y = pack_bf16(v0.z, v0.w);
    u.z = pack_bf16(v1.x, v1.y);
    u.w = pack_bf16(v1.z, v1.w);
    *(uint4*)(dst + off) = u;
}

// ---------------------------------------------------------------------------
// Kernel 1: fused QKV projection, pure bf16, cp.async double-buffered, BK=64.
// C = bf16(Xb @ Wb + b). 128x64 tile, 256 threads (8 warps, 4x2 warp grid).
// ---------------------------------------------------------------------------
__global__ __launch_bounds__(256)
void qkv_gemm(const float* __restrict__ bq, const float* __restrict__ bk,
              const float* __restrict__ bv)
{
    extern __shared__ __nv_bfloat16 dsm[];
    __nv_bfloat16* Xs[2] = {dsm, dsm + 128 * 72};
    __nv_bfloat16* Ws[2] = {dsm + 2 * 128 * 72, dsm + 2 * 128 * 72 + 64 * 72};

    int z = blockIdx.z;
    const __nv_bfloat16* Xg = g_Xb;
    const __nv_bfloat16* Wg = g_Wb[z];
    const float* bias = (z == 0) ? bq : (z == 1) ? bk : bv;
    __nv_bfloat16* C = g_QKV[z];

    int row0 = blockIdx.y * 128;
    int col0 = blockIdx.x * 64;
    int tid  = threadIdx.x;
    int warp = tid >> 5, lane = tid & 31;
    int g = lane >> 2, t4 = lane & 3;
    int wm = (warp & 3) * 32;
    int wn = (warp >> 2) * 32;

    // ldmatrix lane constants
    int a_r = ((lane >> 3) & 1) * 8 + (lane & 7);   // A non-trans
    int a_c = (lane >> 4) * 8;
    int v_r = (lane & 7) + ((lane >> 3) & 1) * 8;   // B trans
    int v_s = lane >> 4;

    // staging chunk coords (16B chunks)
    int xrw[4], xce[4];
    #pragma unroll
    for (int it = 0; it < 4; ++it) {
        int c = tid + it * 256;
        xrw[it] = c >> 3; xce[it] = (c & 7) * 8;
    }
    int wrw[2], wce[2];
    #pragma unroll
    for (int it = 0; it < 2; ++it) {
        int c = tid + it * 256;
        wrw[it] = c >> 3; wce[it] = (c & 7) * 8;
    }

    auto stage = [&](int kit, int buf) {
        int k0 = kit * 64;
        #pragma unroll
        for (int it = 0; it < 4; ++it)
            cpa16(&Xs[buf][xrw[it] * 72 + xce[it]],
                  Xg + (size_t)(row0 + xrw[it]) * DD + k0 + xce[it]);
        #pragma unroll
        for (int it = 0; it < 2; ++it)
            cpa16(&Ws[buf][wrw[it] * 72 + wce[it]],
                  Wg + (size_t)(k0 + wrw[it]) * DD + col0 + wce[it]);
    };

    float acc[2][4][4] = {};

    stage(0, 0); CP_COMMIT;

    for (int it = 0; it < 8; ++it) {
        int buf = it & 1;
        if (it < 7) { stage(it + 1, buf ^ 1); CP_COMMIT; CP_WAIT1; }
        else        { CP_WAIT0; }
        __syncthreads();

        #pragma unroll
        for (int ch = 0; ch < 4; ++ch) {
            int kk = ch * 16;
            uint32_t a[2][4];
            ldm_x4(a[0], &Xs[buf][(wm + a_r) * 72 + kk + a_c]);
            ldm_x4(a[1], &Xs[buf][(wm + 16 + a_r) * 72 + kk + a_c]);
            uint32_t b0[4], b1[4];
            ldm_x4_trans(b0, &Ws[buf][(kk + v_r) * 72 + wn + v_s * 8]);
            ldm_x4_trans(b1, &Ws[buf][(kk + v_r) * 72 + wn + 16 + v_s * 8]);
            #pragma unroll
            for (int m = 0; m < 2; ++m) {
                mma16(acc[m][0], a[m], b0[0], b0[1], acc[m][0]);
                mma16(acc[m][1], a[m], b0[2], b0[3], acc[m][1]);
                mma16(acc[m][2], a[m], b1[0], b1[1], acc[m][2]);
                mma16(acc[m][3], a[m], b1[2], b1[3], acc[m][3]);
            }
        }
        __syncthreads();
    }

    // epilogue: + bias, pack to bf16
    #pragma unroll
    for (int n = 0; n < 4; ++n) {
        int col = col0 + wn + n * 8 + 2 * t4;
        float2 bb = *(const float2*)(bias + col);
        #pragma unroll
        for (int m = 0; m < 2; ++m) {
            int r0 = row0 + wm + m * 16 + g;
            *(uint32_t*)(C + (size_t)r0 * DD + col) =
                pack_bf16(acc[m][n][0] + bb.x, acc[m][n][1] + bb.y);
            *(uint32_t*)(C + (size_t)(r0 + 8) * DD + col) =
                pack_bf16(acc[m][n][2] + bb.x, acc[m][n][3] + bb.y);
        }
    }
}

// ---------------------------------------------------------------------------
// Kernel 2: c[row] = (x[row] . w_g[D:2D]) * log2e   (a_i + b_g cancel; log2e
// folded so attention softmax runs in the log2 domain)
// ---------------------------------------------------------------------------
__global__ __launch_bounds__(256)
void gate_kernel(const float* __restrict__ x, const float* __restrict__ wg)
{
    int row  = blockIdx.x * 8 + (threadIdx.x >> 5);
    int lane = threadIdx.x & 31;
    const float* xr = x + (size_t)row * DD;
    const float* w2 = wg + DD;
    float s = 0.f;
    #pragma unroll 4
    for (int d = lane; d < DD; d += 32) s = fmaf(xr[d], w2[d], s);
    #pragma unroll
    for (int off = 16; off > 0; off >>= 1)
        s += __shfl_xor_sync(0xffffffffu, s, off);
    if (lane == 0) g_c[row] = s * LOG2E;
}

// ---------------------------------------------------------------------------
// Kernel 3: flash attention, bf16 mma, cp.async double-buffered K/V,
// softmax in log2 domain on MUFU (ex2.approx).
// CTA = (64-query tile, h, b), 128 threads = 4 warps x 16 query rows.
// exp-domain identity: softmax(t + log(adj+eps)) ∝ (adj+eps) * 2^(t*log2e - m)
// ---------------------------------------------------------------------------
__global__ __launch_bounds__(128, 4)
void attn_kernel(const float* __restrict__ x, const float* __restrict__ adj,
                 float* __restrict__ out)
{
    __shared__ __nv_bfloat16 Ks[2][64 * 72];
    __shared__ __nv_bfloat16 Vs[2][64 * 72];
    __shared__ __nv_bfloat16 Ps[64 * 72];   // Q staging, then P

    int tid  = threadIdx.x;
    int warp = tid >> 5, lane = tid & 31;
    int g = lane >> 2, t4 = lane & 3;
    int qr = warp * 16;
    int i0 = blockIdx.x * 64;
    int h  = blockIdx.y;
    int b  = blockIdx.z;

    // ldmatrix lane constants
    int a_r = ((lane >> 3) & 1) * 8 + (lane & 7);   // A non-trans (Q, P)
    int a_c = (lane >> 4) * 8;
    int k_r = (lane >> 4) * 8 + (lane & 7);         // B non-trans (K)
    int k_c = ((lane >> 3) & 1) * 8;
    int v_r = (lane & 7) + ((lane >> 3) & 1) * 8;   // B trans (V)
    int v_s = lane >> 4;

    const __nv_bfloat16* Qg = g_QKV[0] + (size_t)b * NN * DD + h * HD;
    const __nv_bfloat16* Kg = g_QKV[1] + (size_t)b * NN * DD + h * HD;
    const __nv_bfloat16* Vg = g_QKV[2] + (size_t)b * NN * DD + h * HD;
    const float* cv   = g_c + b * NN;
    const float* adjb = adj + (size_t)b * NN * NN;

    // staging chunk coords: 64 rows x 8 chunks = 512 chunks / 128 thr = 4
    int srw[4], sce[4];
    #pragma unroll
    for (int it = 0; it < 4; ++it) {
        int c = tid + it * 128;
        srw[it] = c >> 3; sce[it] = (c & 7) * 8;
    }

    auto stage_kv = [&](int jt, int buf) {
        int j0 = jt * 64;
        #pragma unroll
        for (int it = 0; it < 4; ++it) {
            cpa16(&Ks[buf][srw[it] * 72 + sce[it]],
                  Kg + (size_t)(j0 + srw[it]) * DD + sce[it]);
            cpa16(&Vs[buf][srw[it] * 72 + sce[it]],
                  Vg + (size_t)(j0 + srw[it]) * DD + sce[it]);
        }
    };

    // ---- Stage Q tile into Ps; lift A fragments ----
    #pragma unroll
    for (int it = 0; it < 4; ++it) {
        int c = tid + it * 128;
        int r = c >> 3, c8 = (c & 7) * 8;
        uint4 v = *(const uint4*)(Qg + (size_t)(i0 + r) * DD + c8);
        *(uint4*)&Ps[r * 72 + c8] = v;
    }
    stage_kv(0, 0); CP_COMMIT;
    __syncthreads();

    uint32_t qa[4][4];
    #pragma unroll
    for (int ch = 0; ch < 4; ++ch)
        ldm_x4(qa[ch], &Ps[(qr + a_r) * 72 + ch * 16 + a_c]);

    const float SC = 0.125f * LOG2E;   // 1/sqrt(64) * log2e
    float m0 = -1e30f, m1 = -1e30f, l0 = 0.f, l1 = 0.f;
    float o[8][4] = {};

    for (int jt = 0; jt < NN / 64; ++jt) {
        int j0 = jt * 64;
        int buf = jt & 1;
        if (jt + 1 < NN / 64) { stage_kv(jt + 1, buf ^ 1); CP_COMMIT; CP_WAIT1; }
        else                  { CP_WAIT0; }
        __syncthreads();

        // ---- S = Q K^T : warp computes 16x64 ----
        float s[8][4] = {};
        #pragma unroll
        for (int ch = 0; ch < 4; ++ch) {
            int kk = ch * 16;
            #pragma unroll
            for (int np = 0; np < 4; ++np) {
                uint32_t kb[4];
                ldm_x4(kb, &Ks[buf][(np * 16 + k_r) * 72 + kk + k_c]);
                mma16(s[2 * np],     qa[ch], kb[0], kb[1], s[2 * np]);
                mma16(s[2 * np + 1], qa[ch], kb[2], kb[3], s[2 * np + 1]);
            }
        }

        // ---- tt = s*SC + c_j (log2 domain); row max ----
        float mt0 = -1e30f, mt1 = -1e30f;
        #pragma unroll
        for (int n = 0; n < 8; ++n) {
            float2 cc = *(const float2*)(cv + j0 + n * 8 + 2 * t4);
            s[n][0] = fmaf(s[n][0], SC, cc.x);
            s[n][1] = fmaf(s[n][1], SC, cc.y);
            s[n][2] = fmaf(s[n][2], SC, cc.x);
            s[n][3] = fmaf(s[n][3], SC, cc.y);
            mt0 = fmaxf(mt0, fmaxf(s[n][0], s[n][1]));
            mt1 = fmaxf(mt1, fmaxf(s[n][2], s[n][3]));
        }
        mt0 = fmaxf(mt0, __shfl_xor_sync(0xffffffffu, mt0, 1));
        mt0 = fmaxf(mt0, __shfl_xor_sync(0xffffffffu, mt0, 2));
        mt1 = fmaxf(mt1, __shfl_xor_sync(0xffffffffu, mt1, 1));
        mt1 = fmaxf(mt1, __shfl_xor_sync(0xffffffffu, mt1, 2));

        float m0n = fmaxf(m0, mt0), m1n = fmaxf(m1, mt1);
        float a0 = ex2f(m0 - m0n), a1 = ex2f(m1 - m1n);
        m0 = m0n; m1 = m1n;

        // ---- p = (adj+eps) * 2^(tt-m); store bf16 P; row sums ----
        float rs0 = 0.f, rs1 = 0.f;
        int r0 = i0 + qr + g, r1 = r0 + 8;
        #pragma unroll
        for (int n = 0; n < 8; ++n) {
            int jc = j0 + n * 8 + 2 * t4;
            float2 ad0 = *(const float2*)(adjb + (size_t)r0 * NN + jc);
            float2 ad1 = *(const float2*)(adjb + (size_t)r1 * NN + jc);
            float p00 = ex2f(s[n][0] - m0) * (ad0.x + 1e-9f);
            float p01 = ex2f(s[n][1] - m0) * (ad0.y + 1e-9f);
            float p10 = ex2f(s[n][2] - m1) * (ad1.x + 1e-9f);
            float p11 = ex2f(s[n][3] - m1) * (ad1.y + 1e-9f);
            rs0 += p00 + p01; rs1 += p10 + p11;
            *(uint32_t*)&Ps[(qr + g) * 72 + n * 8 + 2 * t4]     = pack_bf16(p00, p01);
            *(uint32_t*)&Ps[(qr + g + 8) * 72 + n * 8 + 2 * t4] = pack_bf16(p10, p11);
        }
        rs0 += __shfl_xor_sync(0xffffffffu, rs0, 1);
        rs0 += __shfl_xor_sync(0xffffffffu, rs0, 2);
        rs1 += __shfl_xor_sync(0xffffffffu, rs1, 1);
        rs1 += __shfl_xor_sync(0xffffffffu, rs1, 2);
        l0 = l0 * a0 + rs0;
        l1 = l1 * a1 + rs1;

        #pragma unroll
        for (int n = 0; n < 8; ++n) {
            o[n][0] *= a0; o[n][1] *= a0; o[n][2] *= a1; o[n][3] *= a1;
        }
        __syncwarp();   // P rows are warp-private

        // ---- O += P @ V ----
        #pragma unroll
        for (int ch = 0; ch < 4; ++ch) {
            int kk = ch * 16;
            uint32_t pa[4];
            ldm_x4(pa, &Ps[(qr + a_r) * 72 + kk + a_c]);
            #pragma unroll
            for (int np = 0; np < 4; ++np) {
                uint32_t vb[4];
                ldm_x4_trans(vb, &Vs[buf][(kk + v_r) * 72 + (2 * np + v_s) * 8]);
                mma16(o[2 * np],     pa, vb[0], vb[1], o[2 * np]);
                mma16(o[2 * np + 1], pa, vb[2], vb[3], o[2 * np + 1]);
            }
        }
        __syncthreads();
    }

    // ---- epilogue: normalize + residual (fp32) ----
    float inv0 = __fdividef(1.0f, l0);
    float inv1 = __fdividef(1.0f, l1);
    int r0 = i0 + qr + g, r1 = r0 + 8;
    #pragma unroll
    for (int n = 0; n < 8; ++n) {
        int col = h * HD + n * 8 + 2 * t4;
        float2 x0 = *(const float2*)(x + ((size_t)b * NN + r0) * DD + col);
        float2 x1 = *(const float2*)(x + ((size_t)b * NN + r1) * DD + col);
        float2 o0 = {fmaf(o[n][0], inv0, x0.x), fmaf(o[n][1], inv0, x0.y)};
        float2 o1 = {fmaf(o[n][2], inv1, x1.x), fmaf(o[n][3], inv1, x1.y)};
        *(float2*)(out + ((size_t)b * NN + r0) * DD + col) = o0;
        *(float2*)(out + ((size_t)b * NN + r1) * DD + col) = o1;
    }
}

// ---------------------------------------------------------------------------
extern "C" void kernel_launch(void* const* d_in, const int* in_sizes, int n_in,
                              void* d_out, int out_size)
{
    const float* x   = (const float*)d_in[0];
    const float* adj = (const float*)d_in[1];
    const float* Wq  = (const float*)d_in[2];
    const float* bq  = (const float*)d_in[3];
    const float* Wk  = (const float*)d_in[4];
    const float* bk  = (const float*)d_in[5];
    const float* Wv  = (const float*)d_in[6];
    const float* bv  = (const float*)d_in[7];
    const float* wg  = (const float*)d_in[8];
    // d_in[9] (b_g) cancels inside the softmax; unused.
    float* out = (float*)d_out;

    const int qkv_smem = (2 * 128 * 72 + 2 * 64 * 72) * 2;   // 55296 B
    cudaFuncSetAttribute((const void*)qkv_gemm,
                         cudaFuncAttributeMaxDynamicSharedMemorySize, qkv_smem);

    convert_kernel<<<1408, 256>>>(x, Wq, Wk, Wv);
    gate_kernel<<<ROWS / 8, 256>>>(x, wg);
    qkv_gemm<<<dim3(DD / 64, ROWS / 128, 3), 256, qkv_smem>>>(bq, bk, bv);
    attn_kernel<<<dim3(NN / 64, HH, BB), 128>>>(x, adj, out);
}

// round 7
// speedup vs baseline: 6.1214x; 1.1156x over previous
#include <cuda_runtime.h>
#include <cuda_bf16.h>
#include <cstdint>

#define BB 2
#define NN 2048
#define DD 512
#define HH 8
#define HD 64
#define ROWS (BB*NN)

// Scratch (no allocations allowed)
__device__ __nv_bfloat16 g_QKV[3][(size_t)ROWS * DD];   // Q,K,V projections
__device__ __nv_bfloat16 g_Xb[(size_t)ROWS * DD];       // x in bf16
__device__ __nv_bfloat16 g_Wb[3][(size_t)DD * DD];      // W_q/k/v in bf16
__device__ float g_c[ROWS];                             // gate vec (pre-scaled by log2e)

#define LOG2E 1.4426950408889634f

// ---------------------------------------------------------------------------
// helpers
// ---------------------------------------------------------------------------
__device__ __forceinline__ float ex2f(float x) {        // 2^x on MUFU
    float r;
    asm("ex2.approx.f32 %0, %1;" : "=f"(r) : "f"(x));
    return r;
}
__device__ __forceinline__ uint32_t pack_bf16(float lo, float hi) {
    uint32_t r;
    asm("cvt.rn.bf16x2.f32 %0, %1, %2;" : "=r"(r) : "f"(hi), "f"(lo));
    return r;
}
__device__ __forceinline__ void mma16(float* d, const uint32_t* a,
                                      uint32_t b0, uint32_t b1, const float* c) {
    asm("mma.sync.aligned.m16n8k16.row.col.f32.bf16.bf16.f32 "
        "{%0,%1,%2,%3}, {%4,%5,%6,%7}, {%8,%9}, {%10,%11,%12,%13};"
        : "=f"(d[0]), "=f"(d[1]), "=f"(d[2]), "=f"(d[3])
        : "r"(a[0]), "r"(a[1]), "r"(a[2]), "r"(a[3]),
          "r"(b0), "r"(b1),
          "f"(c[0]), "f"(c[1]), "f"(c[2]), "f"(c[3]));
}
__device__ __forceinline__ void ldm_x4(uint32_t* r, const void* ptr) {
    uint32_t a = (uint32_t)__cvta_generic_to_shared(ptr);
    asm volatile("ldmatrix.sync.aligned.m8n8.x4.shared.b16 "
                 "{%0,%1,%2,%3}, [%4];"
                 : "=r"(r[0]), "=r"(r[1]), "=r"(r[2]), "=r"(r[3]) : "r"(a));
}
__device__ __forceinline__ void ldm_x4_trans(uint32_t* r, const void* ptr) {
    uint32_t a = (uint32_t)__cvta_generic_to_shared(ptr);
    asm volatile("ldmatrix.sync.aligned.m8n8.x4.trans.shared.b16 "
                 "{%0,%1,%2,%3}, [%4];"
                 : "=r"(r[0]), "=r"(r[1]), "=r"(r[2]), "=r"(r[3]) : "r"(a));
}
__device__ __forceinline__ void cpa16(void* smem_dst, const void* gsrc) {
    uint32_t d = (uint32_t)__cvta_generic_to_shared(smem_dst);
    asm volatile("cp.async.cg.shared.global [%0], [%1], 16;" :: "r"(d), "l"(gsrc));
}
#define CP_COMMIT asm volatile("cp.async.commit_group;" ::: "memory")
#define CP_WAIT1  asm volatile("cp.async.wait_group 1;" ::: "memory")
#define CP_WAIT0  asm volatile("cp.async.wait_group 0;" ::: "memory")

// ---------------------------------------------------------------------------
// Kernel 0: one-shot fp32 -> bf16 conversion of x and W_q/k/v.
// ---------------------------------------------------------------------------
__global__ __launch_bounds__(256)
void convert_kernel(const float* __restrict__ X, const float* __restrict__ Wq,
                    const float* __restrict__ Wk, const float* __restrict__ Wv)
{
    int idx = blockIdx.x * 256 + threadIdx.x;
    const float* src;
    __nv_bfloat16* dst;
    size_t off;
    if (idx < 262144) {                       // X: 2097152 elems / 8
        src = X; dst = g_Xb; off = (size_t)idx * 8;
    } else {
        int r = idx - 262144;
        int z = r >> 15;                      // 32768 chunks per W
        int o = r & 32767;
        src = (z == 0) ? Wq : (z == 1) ? Wk : Wv;
        dst = g_Wb[z]; off = (size_t)o * 8;
    }
    float4 v0 = *(const float4*)(src + off);
    float4 v1 = *(const float4*)(src + off + 4);
    uint4 u;
    u.x = pack_bf16(v0.x, v0.y);
    u.y = pack_bf16(v0.z, v0.w);
    u.z = pack_bf16(v1.x, v1.y);
    u.w = pack_bf16(v1.z, v1.w);
    *(uint4*)(dst + off) = u;
}

// ---------------------------------------------------------------------------
// Kernel 1: fused QKV projection, pure bf16, cp.async double-buffered, BK=64.
// ---------------------------------------------------------------------------
__global__ __launch_bounds__(256)
void qkv_gemm(const float* __restrict__ bq, const float* __restrict__ bk,
              const float* __restrict__ bv)
{
    extern __shared__ __nv_bfloat16 dsm[];
    __nv_bfloat16* Xs[2] = {dsm, dsm + 128 * 72};
    __nv_bfloat16* Ws[2] = {dsm + 2 * 128 * 72, dsm + 2 * 128 * 72 + 64 * 72};

    int z = blockIdx.z;
    const __nv_bfloat16* Xg = g_Xb;
    const __nv_bfloat16* Wg = g_Wb[z];
    const float* bias = (z == 0) ? bq : (z == 1) ? bk : bv;
    __nv_bfloat16* C = g_QKV[z];

    int row0 = blockIdx.y * 128;
    int col0 = blockIdx.x * 64;
    int tid  = threadIdx.x;
    int warp = tid >> 5, lane = tid & 31;
    int g = lane >> 2, t4 = lane & 3;
    int wm = (warp & 3) * 32;
    int wn = (warp >> 2) * 32;

    int a_r = ((lane >> 3) & 1) * 8 + (lane & 7);
    int a_c = (lane >> 4) * 8;
    int v_r = (lane & 7) + ((lane >> 3) & 1) * 8;
    int v_s = lane >> 4;

    int xrw[4], xce[4];
    #pragma unroll
    for (int it = 0; it < 4; ++it) {
        int c = tid + it * 256;
        xrw[it] = c >> 3; xce[it] = (c & 7) * 8;
    }
    int wrw[2], wce[2];
    #pragma unroll
    for (int it = 0; it < 2; ++it) {
        int c = tid + it * 256;
        wrw[it] = c >> 3; wce[it] = (c & 7) * 8;
    }

    auto stage = [&](int kit, int buf) {
        int k0 = kit * 64;
        #pragma unroll
        for (int it = 0; it < 4; ++it)
            cpa16(&Xs[buf][xrw[it] * 72 + xce[it]],
                  Xg + (size_t)(row0 + xrw[it]) * DD + k0 + xce[it]);
        #pragma unroll
        for (int it = 0; it < 2; ++it)
            cpa16(&Ws[buf][wrw[it] * 72 + wce[it]],
                  Wg + (size_t)(k0 + wrw[it]) * DD + col0 + wce[it]);
    };

    float acc[2][4][4] = {};

    stage(0, 0); CP_COMMIT;

    for (int it = 0; it < 8; ++it) {
        int buf = it & 1;
        if (it < 7) { stage(it + 1, buf ^ 1); CP_COMMIT; CP_WAIT1; }
        else        { CP_WAIT0; }
        __syncthreads();

        #pragma unroll
        for (int ch = 0; ch < 4; ++ch) {
            int kk = ch * 16;
            uint32_t a[2][4];
            ldm_x4(a[0], &Xs[buf][(wm + a_r) * 72 + kk + a_c]);
            ldm_x4(a[1], &Xs[buf][(wm + 16 + a_r) * 72 + kk + a_c]);
            uint32_t b0[4], b1[4];
            ldm_x4_trans(b0, &Ws[buf][(kk + v_r) * 72 + wn + v_s * 8]);
            ldm_x4_trans(b1, &Ws[buf][(kk + v_r) * 72 + wn + 16 + v_s * 8]);
            #pragma unroll
            for (int m = 0; m < 2; ++m) {
                mma16(acc[m][0], a[m], b0[0], b0[1], acc[m][0]);
                mma16(acc[m][1], a[m], b0[2], b0[3], acc[m][1]);
                mma16(acc[m][2], a[m], b1[0], b1[1], acc[m][2]);
                mma16(acc[m][3], a[m], b1[2], b1[3], acc[m][3]);
            }
        }
        __syncthreads();
    }

    #pragma unroll
    for (int n = 0; n < 4; ++n) {
        int col = col0 + wn + n * 8 + 2 * t4;
        float2 bb = *(const float2*)(bias + col);
        #pragma unroll
        for (int m = 0; m < 2; ++m) {
            int r0 = row0 + wm + m * 16 + g;
            *(uint32_t*)(C + (size_t)r0 * DD + col) =
                pack_bf16(acc[m][n][0] + bb.x, acc[m][n][1] + bb.y);
            *(uint32_t*)(C + (size_t)(r0 + 8) * DD + col) =
                pack_bf16(acc[m][n][2] + bb.x, acc[m][n][3] + bb.y);
        }
    }
}

// ---------------------------------------------------------------------------
// Kernel 2: c[row] = (x[row] . w_g[D:2D]) * log2e
// ---------------------------------------------------------------------------
__global__ __launch_bounds__(256)
void gate_kernel(const float* __restrict__ x, const float* __restrict__ wg)
{
    int row  = blockIdx.x * 8 + (threadIdx.x >> 5);
    int lane = threadIdx.x & 31;
    const float* xr = x + (size_t)row * DD;
    const float* w2 = wg + DD;
    float s = 0.f;
    #pragma unroll 4
    for (int d = lane; d < DD; d += 32) s = fmaf(xr[d], w2[d], s);
    #pragma unroll
    for (int off = 16; off > 0; off >>= 1)
        s += __shfl_xor_sync(0xffffffffu, s, off);
    if (lane == 0) g_c[row] = s * LOG2E;
}

// ---------------------------------------------------------------------------
// Kernel 3: flash attention, bf16 mma, cp.async TRIPLE-buffered K/V (one
// barrier per iter), P kept entirely in registers (S C-fragment == PV
// A-fragment layout), softmax in log2 domain on MUFU.
// CTA = (64-query tile, h, b), 128 threads = 4 warps x 16 query rows.
// ---------------------------------------------------------------------------
__global__ __launch_bounds__(128, 4)
void attn_kernel(const float* __restrict__ x, const float* __restrict__ adj,
                 float* __restrict__ out)
{
    extern __shared__ __nv_bfloat16 asm_buf[];
    const int TB = 64 * 72;
    // K buffers 0..2, V buffers 0..2; Q staged in V buffer 2 pre-loop.
    __nv_bfloat16* Kb0 = asm_buf;
    __nv_bfloat16* Vb0 = asm_buf + 3 * TB;

    int tid  = threadIdx.x;
    int warp = tid >> 5, lane = tid & 31;
    int g = lane >> 2, t4 = lane & 3;
    int qr = warp * 16;
    int i0 = blockIdx.x * 64;
    int h  = blockIdx.y;
    int b  = blockIdx.z;

    int a_r = ((lane >> 3) & 1) * 8 + (lane & 7);   // A non-trans (Q)
    int a_c = (lane >> 4) * 8;
    int k_r = (lane >> 4) * 8 + (lane & 7);         // B non-trans (K)
    int k_c = ((lane >> 3) & 1) * 8;
    int v_r = (lane & 7) + ((lane >> 3) & 1) * 8;   // B trans (V)
    int v_s = lane >> 4;

    const __nv_bfloat16* Qg = g_QKV[0] + (size_t)b * NN * DD + h * HD;
    const __nv_bfloat16* Kg = g_QKV[1] + (size_t)b * NN * DD + h * HD;
    const __nv_bfloat16* Vg = g_QKV[2] + (size_t)b * NN * DD + h * HD;
    const float* cv   = g_c + b * NN;
    const float* adjb = adj + (size_t)b * NN * NN;

    int srw[4], sce[4];
    #pragma unroll
    for (int it = 0; it < 4; ++it) {
        int c = tid + it * 128;
        srw[it] = c >> 3; sce[it] = (c & 7) * 8;
    }

    auto stage_kv = [&](int jt, int buf) {
        int j0 = jt * 64;
        #pragma unroll
        for (int it = 0; it < 4; ++it) {
            cpa16(Kb0 + buf * TB + srw[it] * 72 + sce[it],
                  Kg + (size_t)(j0 + srw[it]) * DD + sce[it]);
            cpa16(Vb0 + buf * TB + srw[it] * 72 + sce[it],
                  Vg + (size_t)(j0 + srw[it]) * DD + sce[it]);
        }
    };

    // ---- Stage Q into V buffer 2 (free until iter 2's staging) ----
    __nv_bfloat16* Qs = Vb0 + 2 * TB;
    #pragma unroll
    for (int it = 0; it < 4; ++it) {
        uint4 v = *(const uint4*)(Qg + (size_t)(i0 + srw[it]) * DD + sce[it]);
        *(uint4*)&Qs[srw[it] * 72 + sce[it]] = v;
    }
    stage_kv(0, 0); CP_COMMIT;
    __syncthreads();

    uint32_t qa[4][4];
    #pragma unroll
    for (int ch = 0; ch < 4; ++ch)
        ldm_x4(qa[ch], &Qs[(qr + a_r) * 72 + ch * 16 + a_c]);
    // NOTE: first loop barrier (iter 0) guarantees all warps lifted qa before
    // iter 1 stages buffer 2 (which overwrites Qs at iter 1's stage call?
    // iter 1 stages buf (1+1)%3 = 2 — protected by iter 0's barrier).

    const float SC = 0.125f * LOG2E;
    float m0 = -1e30f, m1 = -1e30f, l0 = 0.f, l1 = 0.f;
    float o[8][4] = {};

    for (int jt = 0; jt < NN / 64; ++jt) {
        int j0 = jt * 64;
        int buf = jt % 3;
        if (jt + 1 < NN / 64) { stage_kv(jt + 1, (jt + 1) % 3); CP_COMMIT; CP_WAIT1; }
        else                  { CP_WAIT0; }
        __syncthreads();

        const __nv_bfloat16* Kt = Kb0 + buf * TB;
        const __nv_bfloat16* Vt = Vb0 + buf * TB;

        // ---- S = Q K^T ----
        float s[8][4] = {};
        #pragma unroll
        for (int ch = 0; ch < 4; ++ch) {
            int kk = ch * 16;
            #pragma unroll
            for (int np = 0; np < 4; ++np) {
                uint32_t kb[4];
                ldm_x4(kb, &Kt[(np * 16 + k_r) * 72 + kk + k_c]);
                mma16(s[2 * np],     qa[ch], kb[0], kb[1], s[2 * np]);
                mma16(s[2 * np + 1], qa[ch], kb[2], kb[3], s[2 * np + 1]);
            }
        }

        // ---- tt = s*SC + c_j (log2 domain); row max ----
        float mt0 = -1e30f, mt1 = -1e30f;
        #pragma unroll
        for (int n = 0; n < 8; ++n) {
            float2 cc = *(const float2*)(cv + j0 + n * 8 + 2 * t4);
            s[n][0] = fmaf(s[n][0], SC, cc.x);
            s[n][1] = fmaf(s[n][1], SC, cc.y);
            s[n][2] = fmaf(s[n][2], SC, cc.x);
            s[n][3] = fmaf(s[n][3], SC, cc.y);
            mt0 = fmaxf(mt0, fmaxf(s[n][0], s[n][1]));
            mt1 = fmaxf(mt1, fmaxf(s[n][2], s[n][3]));
        }
        mt0 = fmaxf(mt0, __shfl_xor_sync(0xffffffffu, mt0, 1));
        mt0 = fmaxf(mt0, __shfl_xor_sync(0xffffffffu, mt0, 2));
        mt1 = fmaxf(mt1, __shfl_xor_sync(0xffffffffu, mt1, 1));
        mt1 = fmaxf(mt1, __shfl_xor_sync(0xffffffffu, mt1, 2));

        float m0n = fmaxf(m0, mt0), m1n = fmaxf(m1, mt1);
        float a0 = ex2f(m0 - m0n), a1 = ex2f(m1 - m1n);
        m0 = m0n; m1 = m1n;

        // ---- p = (adj+eps)*2^(tt-m) packed DIRECTLY into PV A-fragments ----
        // (S C-fragment layout == P A-fragment layout; no smem round-trip)
        uint32_t pa[4][4];
        float rs0 = 0.f, rs1 = 0.f;
        int r0 = i0 + qr + g, r1 = r0 + 8;
        #pragma unroll
        for (int ch = 0; ch < 4; ++ch) {
            #pragma unroll
            for (int w = 0; w < 2; ++w) {
                int n = 2 * ch + w;
                int jc = j0 + n * 8 + 2 * t4;
                float2 ad0 = *(const float2*)(adjb + (size_t)r0 * NN + jc);
                float2 ad1 = *(const float2*)(adjb + (size_t)r1 * NN + jc);
                float p00 = ex2f(s[n][0] - m0) * (ad0.x + 1e-9f);
                float p01 = ex2f(s[n][1] - m0) * (ad0.y + 1e-9f);
                float p10 = ex2f(s[n][2] - m1) * (ad1.x + 1e-9f);
                float p11 = ex2f(s[n][3] - m1) * (ad1.y + 1e-9f);
                rs0 += p00 + p01; rs1 += p10 + p11;
                pa[ch][2 * w]     = pack_bf16(p00, p01);
                pa[ch][2 * w + 1] = pack_bf16(p10, p11);
            }
        }
        rs0 += __shfl_xor_sync(0xffffffffu, rs0, 1);
        rs0 += __shfl_xor_sync(0xffffffffu, rs0, 2);
        rs1 += __shfl_xor_sync(0xffffffffu, rs1, 1);
        rs1 += __shfl_xor_sync(0xffffffffu, rs1, 2);
        l0 = l0 * a0 + rs0;
        l1 = l1 * a1 + rs1;

        #pragma unroll
        for (int n = 0; n < 8; ++n) {
            o[n][0] *= a0; o[n][1] *= a0; o[n][2] *= a1; o[n][3] *= a1;
        }

        // ---- O += P @ V (P from registers) ----
        #pragma unroll
        for (int ch = 0; ch < 4; ++ch) {
            int kk = ch * 16;
            #pragma unroll
            for (int np = 0; np < 4; ++np) {
                uint32_t vb[4];
                ldm_x4_trans(vb, &Vt[(kk + v_r) * 72 + (2 * np + v_s) * 8]);
                mma16(o[2 * np],     pa[ch], vb[0], vb[1], o[2 * np]);
                mma16(o[2 * np + 1], pa[ch], vb[2], vb[3], o[2 * np + 1]);
            }
        }
    }

    // ---- epilogue: normalize + residual (fp32) ----
    float inv0 = __fdividef(1.0f, l0);
    float inv1 = __fdividef(1.0f, l1);
    int r0 = i0 + qr + g, r1 = r0 + 8;
    #pragma unroll
    for (int n = 0; n < 8; ++n) {
        int col = h * HD + n * 8 + 2 * t4;
        float2 x0 = *(const float2*)(x + ((size_t)b * NN + r0) * DD + col);
        float2 x1 = *(const float2*)(x + ((size_t)b * NN + r1) * DD + col);
        float2 o0 = {fmaf(o[n][0], inv0, x0.x), fmaf(o[n][1], inv0, x0.y)};
        float2 o1 = {fmaf(o[n][2], inv1, x1.x), fmaf(o[n][3], inv1, x1.y)};
        *(float2*)(out + ((size_t)b * NN + r0) * DD + col) = o0;
        *(float2*)(out + ((size_t)b * NN + r1) * DD + col) = o1;
    }
}

// ---------------------------------------------------------------------------
extern "C" void kernel_launch(void* const* d_in, const int* in_sizes, int n_in,
                              void* d_out, int out_size)
{
    const float* x   = (const float*)d_in[0];
    const float* adj = (const float*)d_in[1];
    const float* Wq  = (const float*)d_in[2];
    const float* bq  = (const float*)d_in[3];
    const float* Wk  = (const float*)d_in[4];
    const float* bk  = (const float*)d_in[5];
    const float* Wv  = (const float*)d_in[6];
    const float* bv  = (const float*)d_in[7];
    const float* wg  = (const float*)d_in[8];
    // d_in[9] (b_g) cancels inside the softmax; unused.
    float* out = (float*)d_out;

    const int qkv_smem = (2 * 128 * 72 + 2 * 64 * 72) * 2;   // 55296 B
    cudaFuncSetAttribute((const void*)qkv_gemm,
                         cudaFuncAttributeMaxDynamicSharedMemorySize, qkv_smem);
    const int attn_smem = 6 * 64 * 72 * 2;                   // 55296 B
    cudaFuncSetAttribute((const void*)attn_kernel,
                         cudaFuncAttributeMaxDynamicSharedMemorySize, attn_smem);

    convert_kernel<<<1408, 256>>>(x, Wq, Wk, Wv);
    gate_kernel<<<ROWS / 8, 256>>>(x, wg);
    qkv_gemm<<<dim3(DD / 64, ROWS / 128, 3), 256, qkv_smem>>>(bq, bk, bv);
    attn_kernel<<<dim3(NN / 64, HH, BB), 128, attn_smem>>>(x, adj, out);
}